// round 7
// baseline (speedup 1.0000x reference)
#include <cuda_runtime.h>
#include <cuda_bf16.h>
#include <cstdint>

#define NN 50000
#define NE 800000
#define INC 165
#define HID 256
#define KP1 192              // K=165 padded to multiple of 64

// ---------------- scratch (no runtime allocation allowed) ----------------
__device__ int   g_cnt[NN];
__device__ int   g_ptr[NN + 1];
__device__ int   g_cursor[NN];
__device__ int   g_csr[NE];
__device__ __nv_bfloat16 g_xh[(size_t)NN * KP1];
__device__ __nv_bfloat16 g_xl[(size_t)NN * KP1];
__device__ __nv_bfloat16 g_z1h[(size_t)NN * KP1];
__device__ __nv_bfloat16 g_z1l[(size_t)NN * KP1];
__device__ __nv_bfloat16 g_h1h[(size_t)NN * HID];
__device__ __nv_bfloat16 g_h1l[(size_t)NN * HID];
__device__ __nv_bfloat16 g_hh[(size_t)NN * HID];
__device__ __nv_bfloat16 g_hl[(size_t)NN * HID];
__device__ __nv_bfloat16 g_z2h[(size_t)NN * HID];
__device__ __nv_bfloat16 g_z2l[(size_t)NN * HID];
__device__ __nv_bfloat16 g_w1a_hi[HID * KP1];
__device__ __nv_bfloat16 g_w1a_lo[HID * KP1];
__device__ __nv_bfloat16 g_w1b_hi[HID * HID];
__device__ __nv_bfloat16 g_w1b_lo[HID * HID];
__device__ __nv_bfloat16 g_w2a_hi[HID * HID];
__device__ __nv_bfloat16 g_w2a_lo[HID * HID];

// ---------------- PTX helpers ----------------
__device__ __forceinline__ uint32_t smem_u32(const void* p) {
    uint32_t a;
    asm("{ .reg .u64 t; cvta.to.shared.u64 t, %1; cvt.u32.u64 %0, t; }" : "=r"(a) : "l"(p));
    return a;
}
__device__ __forceinline__ void ldm_x4(uint32_t* r, uint32_t addr) {
    asm volatile("ldmatrix.sync.aligned.m8n8.x4.shared.b16 {%0,%1,%2,%3}, [%4];"
        : "=r"(r[0]), "=r"(r[1]), "=r"(r[2]), "=r"(r[3]) : "r"(addr));
}
__device__ __forceinline__ void ldm_x2(uint32_t* r, uint32_t addr) {
    asm volatile("ldmatrix.sync.aligned.m8n8.x2.shared.b16 {%0,%1}, [%2];"
        : "=r"(r[0]), "=r"(r[1]) : "r"(addr));
}
__device__ __forceinline__ void mma_bf16(float* c, const uint32_t* a, const uint32_t* b) {
    asm volatile("mma.sync.aligned.m16n8k16.row.col.f32.bf16.bf16.f32 "
        "{%0,%1,%2,%3}, {%4,%5,%6,%7}, {%8,%9}, {%0,%1,%2,%3};"
        : "+f"(c[0]), "+f"(c[1]), "+f"(c[2]), "+f"(c[3])
        : "r"(a[0]), "r"(a[1]), "r"(a[2]), "r"(a[3]), "r"(b[0]), "r"(b[1]));
}
__device__ __forceinline__ void cp16(uint32_t dst, const void* src) {
    asm volatile("cp.async.ca.shared.global [%0], [%1], 16;" :: "r"(dst), "l"(src));
}
__device__ __forceinline__ uint32_t pack2(float v0, float v1) {
    __nv_bfloat162 h = __floats2bfloat162_rn(v0, v1);
    return *(uint32_t*)&h;
}
__device__ __forceinline__ void acc8(float* a, uint4 h, uint4 l) {
    const uint32_t hu[4] = {h.x, h.y, h.z, h.w}, lu[4] = {l.x, l.y, l.z, l.w};
#pragma unroll
    for (int q = 0; q < 4; q++) {
        float2 fh = __bfloat1622float2(*(const __nv_bfloat162*)&hu[q]);
        float2 fl = __bfloat1622float2(*(const __nv_bfloat162*)&lu[q]);
        a[2 * q]     += fh.x + fl.x;
        a[2 * q + 1] += fh.y + fl.y;
    }
}
__device__ __forceinline__ void split8(const float* a, uint4& h, uint4& l) {
    uint32_t hu[4], lu[4];
#pragma unroll
    for (int q = 0; q < 4; q++) {
        float v0 = a[2 * q], v1 = a[2 * q + 1];
        hu[q] = pack2(v0, v1);
        float f0 = __bfloat162float(__float2bfloat16(v0));
        float f1 = __bfloat162float(__float2bfloat16(v1));
        lu[q] = pack2(v0 - f0, v1 - f1);
    }
    h = make_uint4(hu[0], hu[1], hu[2], hu[3]);
    l = make_uint4(lu[0], lu[1], lu[2], lu[3]);
}

// ---------------------------------------------------------------------------
// CSR build
// ---------------------------------------------------------------------------
__global__ void hist_kernel(const int* __restrict__ dst, int* __restrict__ cnt) {
    int e = blockIdx.x * blockDim.x + threadIdx.x;
    if (e < NE) atomicAdd(&cnt[__ldg(dst + e)], 1);
}

__global__ void scan_kernel(const int* __restrict__ cnt,
                            int* __restrict__ ptr, int* __restrict__ cursor) {
    __shared__ int wsum[32];
    __shared__ int running;
    const int t = threadIdx.x;
    if (t == 0) running = 0;
    __syncthreads();
    for (int base = 0; base < NN; base += 1024) {
        int v = (base + t < NN) ? cnt[base + t] : 0;
        int x = v;
#pragma unroll
        for (int o = 1; o < 32; o <<= 1) {
            int y = __shfl_up_sync(0xffffffffu, x, o);
            if ((t & 31) >= o) x += y;
        }
        if ((t & 31) == 31) wsum[t >> 5] = x;
        __syncthreads();
        if (t < 32) {
            int w = wsum[t];
#pragma unroll
            for (int o = 1; o < 32; o <<= 1) {
                int y = __shfl_up_sync(0xffffffffu, w, o);
                if (t >= o) w += y;
            }
            wsum[t] = w;
        }
        __syncthreads();
        int excl = x - v + ((t >= 32) ? wsum[(t >> 5) - 1] : 0) + running;
        if (base + t < NN) { ptr[base + t] = excl; cursor[base + t] = excl; }
        __syncthreads();
        if (t == 0) running += wsum[31];
        __syncthreads();
    }
    if (t == 0) ptr[NN] = running;
}

__global__ void fill_kernel(const int* __restrict__ src, const int* __restrict__ dst,
                            int* __restrict__ cursor, int* __restrict__ csr) {
    int e = blockIdx.x * blockDim.x + threadIdx.x;
    if (e < NE) {
        int p = atomicAdd(&cursor[__ldg(dst + e)], 1);
        csr[p] = __ldg(src + e);
    }
}

// x [NN][165] fp32 -> planar bf16 hi/lo [NN][192], zero-padded
__global__ void pad_split_kernel(const float* __restrict__ x,
                                 __nv_bfloat16* __restrict__ xh,
                                 __nv_bfloat16* __restrict__ xl) {
    int i = blockIdx.x * blockDim.x + threadIdx.x;
    if (i >= NN * (KP1 / 4)) return;
    int n = i / (KP1 / 4), c = (i % (KP1 / 4)) * 4;
    float v[4];
#pragma unroll
    for (int q = 0; q < 4; q++) {
        int cc = c + q;
        v[q] = (cc < INC) ? __ldg(&x[(size_t)n * INC + cc]) : 0.f;
    }
    uint32_t h0 = pack2(v[0], v[1]), h1 = pack2(v[2], v[3]);
    float f0 = __bfloat162float(__float2bfloat16(v[0]));
    float f1 = __bfloat162float(__float2bfloat16(v[1]));
    float f2 = __bfloat162float(__float2bfloat16(v[2]));
    float f3 = __bfloat162float(__float2bfloat16(v[3]));
    uint32_t l0 = pack2(v[0] - f0, v[1] - f1), l1 = pack2(v[2] - f2, v[3] - f3);
    *(uint32_t*)(xh + (size_t)n * KP1 + c) = h0;
    *(uint32_t*)(xh + (size_t)n * KP1 + c + 2) = h1;
    *(uint32_t*)(xl + (size_t)n * KP1 + c) = l0;
    *(uint32_t*)(xl + (size_t)n * KP1 + c + 2) = l1;
}

// ---------------------------------------------------------------------------
// Gather-aggregate on planar bf16 hi/lo: z[n] = f[n] + sum_nbr f[nbr].
// Warp per node; lane covers 8 columns (one uint4 per plane).
// ---------------------------------------------------------------------------
template<int RU4>   // uint4s per row (24 for K=192, 32 for K=256)
__global__ void gather_kernel(const uint4* __restrict__ fh, const uint4* __restrict__ fl,
                              const int* __restrict__ ptr, const int* __restrict__ csr,
                              uint4* __restrict__ zh, uint4* __restrict__ zl) {
    int n = blockIdx.x * (blockDim.x >> 5) + (threadIdx.x >> 5);
    if (n >= NN) return;
    const int lane = threadIdx.x & 31;
    if (lane >= RU4) return;
    float a[8] = {0, 0, 0, 0, 0, 0, 0, 0};
    acc8(a, __ldg(fh + (size_t)n * RU4 + lane), __ldg(fl + (size_t)n * RU4 + lane));
    const int e0 = __ldg(ptr + n), e1 = __ldg(ptr + n + 1);
    int j = e0;
    for (; j + 1 < e1; j += 2) {
        const size_t b0 = (size_t)__ldg(csr + j) * RU4;
        const size_t b1 = (size_t)__ldg(csr + j + 1) * RU4;
        uint4 h0 = __ldg(fh + b0 + lane), l0 = __ldg(fl + b0 + lane);
        uint4 h1 = __ldg(fh + b1 + lane), l1 = __ldg(fl + b1 + lane);
        acc8(a, h0, l0);
        acc8(a, h1, l1);
    }
    if (j < e1) {
        const size_t b0 = (size_t)__ldg(csr + j) * RU4;
        acc8(a, __ldg(fh + b0 + lane), __ldg(fl + b0 + lane));
    }
    uint4 oh, ol;
    split8(a, oh, ol);
    zh[(size_t)n * RU4 + lane] = oh;
    zl[(size_t)n * RU4 + lane] = ol;
}

// ---------------------------------------------------------------------------
// Weight prep: W[K,N] fp32 -> W^T split bf16 hi/lo, [N][Kp], zero-padded.
// ---------------------------------------------------------------------------
__global__ void prep_w_kernel(const float* __restrict__ W,
                              __nv_bfloat16* __restrict__ hi,
                              __nv_bfloat16* __restrict__ lo,
                              int K, int N, int Kp) {
    int i = blockIdx.x * blockDim.x + threadIdx.x;
    if (i >= N * Kp) return;
    int n = i / Kp, k = i % Kp;
    float w = (k < K) ? __ldg(&W[(size_t)k * N + n]) : 0.f;
    __nv_bfloat16 h = __float2bfloat16(w);
    hi[i] = h;
    lo[i] = __float2bfloat16(w - __bfloat162float(h));
}

__global__ void init_out_kernel(float* __restrict__ out, const float* __restrict__ b2) {
    int i = blockIdx.x * blockDim.x + threadIdx.x;
    if (i < NN * 2) out[i] = __ldg(b2 + (i & 1));
}

// ---------------------------------------------------------------------------
// cp.async-pipelined warp-MMA bf16-split GEMM.
// CTA tile 128x128, 8 warps 4Mx2N, warp tile 32x64. 2-stage ping-pong smem.
// Non-OUTP epilogue: relu(acc+bias) -> planar bf16 hi/lo outputs.
// OUTP: relu(acc+bias) projected on w2[256][2], atomicAdd into Cout[M][2].
// ---------------------------------------------------------------------------
#define SROW 72
#define SMAT (128 * SROW * 2)      // 18432 B per tile
#define OFF_AHI 0
#define OFF_ALO (SMAT)
#define OFF_BHI (2 * SMAT)
#define OFF_BLO (3 * SMAT)
#define STG (4 * SMAT)             // 73728 B per stage
#define SMTOT (2 * STG)            // 147456 B

template<bool OUTP>
__global__ __launch_bounds__(256)
void mma_gemm_kernel(const __nv_bfloat16* __restrict__ Ah,
                     const __nv_bfloat16* __restrict__ Al, int lda,
                     const __nv_bfloat16* __restrict__ Bh,
                     const __nv_bfloat16* __restrict__ Bl, int Kp,
                     const float* __restrict__ bias,
                     __nv_bfloat16* __restrict__ Ch, __nv_bfloat16* __restrict__ Cl,
                     float* __restrict__ Cout, int M,
                     const float* __restrict__ w2) {
    extern __shared__ __align__(16) char smem[];
    const uint32_t sb = smem_u32(smem);
    const int tid = threadIdx.x, wid = tid >> 5, lane = tid & 31;

    const int bm0 = blockIdx.y * 128;
    const int n0 = blockIdx.x * 128;

    const int arow = tid >> 1;
    const int acol0 = (tid & 1) * 32;
    const int mw = (wid >> 1) * 32;
    const int nw = (wid & 1) * 64;

    // source row pointers for the loader (clamped; OOB rows discarded at store)
    const int gRow = bm0 + arow;
    const __nv_bfloat16* pAh = Ah + (size_t)(gRow < M ? gRow : 0) * lda + acol0;
    const __nv_bfloat16* pAl = Al + (size_t)(gRow < M ? gRow : 0) * lda + acol0;
    const __nv_bfloat16* pBh = Bh + (size_t)(n0 + arow) * Kp + acol0;
    const __nv_bfloat16* pBl = Bl + (size_t)(n0 + arow) * Kp + acol0;
    const uint32_t sdst = sb + (uint32_t)(arow * SROW + acol0) * 2;

    const int nchunks = Kp >> 6;

#define PREFETCH(CH)  do { \
        const int _k0 = (CH) << 6; \
        const uint32_t _d = sdst + ((CH) & 1) * STG; \
        _Pragma("unroll") \
        for (int q = 0; q < 4; q++) { \
            cp16(_d + OFF_AHI + q * 16, pAh + _k0 + q * 8); \
            cp16(_d + OFF_ALO + q * 16, pAl + _k0 + q * 8); \
            cp16(_d + OFF_BHI + q * 16, pBh + _k0 + q * 8); \
            cp16(_d + OFF_BLO + q * 16, pBl + _k0 + q * 8); \
        } \
    } while (0)

    PREFETCH(0);
    asm volatile("cp.async.commit_group;" ::: "memory");
    PREFETCH(1);
    asm volatile("cp.async.commit_group;" ::: "memory");

    float acc[2][8][4];
#pragma unroll
    for (int ms = 0; ms < 2; ms++)
#pragma unroll
        for (int ns = 0; ns < 8; ns++)
#pragma unroll
            for (int q = 0; q < 4; q++) acc[ms][ns][q] = 0.f;

    const int l7 = lane & 7;
    const int aRowAdd = ((lane >> 3) & 1) * 8;
    const int aKAdd = (lane >> 4) * 8;
    const int bl = lane & 15;
    const int bRow = bl & 7;
    const int bKAdd = ((bl >> 3) & 1) * 8;

    for (int ch = 0; ch < nchunks; ch++) {
        asm volatile("cp.async.wait_group 1;" ::: "memory");
        __syncthreads();

        const uint32_t st = sb + (ch & 1) * STG;
#pragma unroll
        for (int kk = 0; kk < 64; kk += 16) {
            uint32_t ahi[2][4], alo[2][4], bhi[8][2], blo[8][2];
#pragma unroll
            for (int ms = 0; ms < 2; ms++) {
                uint32_t ra = st + (uint32_t)((mw + ms * 16 + l7 + aRowAdd) * SROW + kk + aKAdd) * 2;
                ldm_x4(ahi[ms], ra + OFF_AHI);
                ldm_x4(alo[ms], ra + OFF_ALO);
            }
#pragma unroll
            for (int ns = 0; ns < 8; ns++) {
                uint32_t rb = st + (uint32_t)((nw + ns * 8 + bRow) * SROW + kk + bKAdd) * 2;
                ldm_x2(bhi[ns], rb + OFF_BHI);
                ldm_x2(blo[ns], rb + OFF_BLO);
            }
#pragma unroll
            for (int ms = 0; ms < 2; ms++)
#pragma unroll
                for (int ns = 0; ns < 8; ns++) {
                    mma_bf16(acc[ms][ns], ahi[ms], bhi[ns]);
                    mma_bf16(acc[ms][ns], alo[ms], bhi[ns]);
                    mma_bf16(acc[ms][ns], ahi[ms], blo[ns]);
                }
        }
        __syncthreads();
        if (ch + 2 < nchunks) PREFETCH(ch + 2);
        asm volatile("cp.async.commit_group;" ::: "memory");
    }
#undef PREFETCH

    const int r = lane >> 2;
    const int cp = (lane & 3) * 2;

    if (OUTP) {
        float s[2][2][2];
#pragma unroll
        for (int ms = 0; ms < 2; ms++)
#pragma unroll
            for (int rh = 0; rh < 2; rh++) { s[ms][rh][0] = 0.f; s[ms][rh][1] = 0.f; }
#pragma unroll
        for (int ms = 0; ms < 2; ms++)
#pragma unroll
            for (int ns = 0; ns < 8; ns++) {
                const int col = n0 + nw + ns * 8 + cp;
                const float2 bb = *(const float2*)(bias + col);
                const float2 w0 = *(const float2*)(w2 + col * 2);
                const float2 w1 = *(const float2*)(w2 + (col + 1) * 2);
                float v0 = fmaxf(acc[ms][ns][0] + bb.x, 0.f);
                float v1 = fmaxf(acc[ms][ns][1] + bb.y, 0.f);
                float v2 = fmaxf(acc[ms][ns][2] + bb.x, 0.f);
                float v3 = fmaxf(acc[ms][ns][3] + bb.y, 0.f);
                s[ms][0][0] += v0 * w0.x + v1 * w1.x;
                s[ms][0][1] += v0 * w0.y + v1 * w1.y;
                s[ms][1][0] += v2 * w0.x + v3 * w1.x;
                s[ms][1][1] += v2 * w0.y + v3 * w1.y;
            }
#pragma unroll
        for (int ms = 0; ms < 2; ms++)
#pragma unroll
            for (int rh = 0; rh < 2; rh++)
#pragma unroll
                for (int oc = 0; oc < 2; oc++) {
                    float v = s[ms][rh][oc];
                    v += __shfl_xor_sync(0xffffffffu, v, 1);
                    v += __shfl_xor_sync(0xffffffffu, v, 2);
                    s[ms][rh][oc] = v;
                }
        if ((lane & 3) == 0) {
#pragma unroll
            for (int ms = 0; ms < 2; ms++)
#pragma unroll
                for (int rh = 0; rh < 2; rh++) {
                    const int row = bm0 + mw + ms * 16 + r + rh * 8;
                    if (row < M) {
                        atomicAdd(Cout + (size_t)row * 2 + 0, s[ms][rh][0]);
                        atomicAdd(Cout + (size_t)row * 2 + 1, s[ms][rh][1]);
                    }
                }
        }
    } else {
#pragma unroll
        for (int ms = 0; ms < 2; ms++)
#pragma unroll
            for (int ns = 0; ns < 8; ns++) {
                const int col = n0 + nw + ns * 8 + cp;
                const float2 bb = *(const float2*)(bias + col);
                const int row0 = bm0 + mw + ms * 16 + r;
                float v0 = fmaxf(acc[ms][ns][0] + bb.x, 0.f);
                float v1 = fmaxf(acc[ms][ns][1] + bb.y, 0.f);
                float v2 = fmaxf(acc[ms][ns][2] + bb.x, 0.f);
                float v3 = fmaxf(acc[ms][ns][3] + bb.y, 0.f);
#pragma unroll
                for (int rh = 0; rh < 2; rh++) {
                    const int row = row0 + rh * 8;
                    if (row >= M) continue;
                    float a0 = rh ? v2 : v0, a1 = rh ? v3 : v1;
                    uint32_t hp = pack2(a0, a1);
                    float f0 = __bfloat162float(__float2bfloat16(a0));
                    float f1 = __bfloat162float(__float2bfloat16(a1));
                    uint32_t lp = pack2(a0 - f0, a1 - f1);
                    *(uint32_t*)(Ch + (size_t)row * HID + col) = hp;
                    *(uint32_t*)(Cl + (size_t)row * HID + col) = lp;
                }
            }
    }
}

// ---------------------------------------------------------------------------
extern "C" void kernel_launch(void* const* d_in, const int* in_sizes, int n_in,
                              void* d_out, int out_size) {
    const float* x   = (const float*)d_in[0];
    const int*   ei  = (const int*)d_in[1];
    const float* W1a = (const float*)d_in[2];
    const float* b1a = (const float*)d_in[3];
    const float* W1b = (const float*)d_in[4];
    const float* b1b = (const float*)d_in[5];
    const float* W2a = (const float*)d_in[6];
    const float* b2a = (const float*)d_in[7];
    const float* W2b = (const float*)d_in[8];
    const float* b2b = (const float*)d_in[9];
    float* out = (float*)d_out;

    const int* src = ei;
    const int* dst = ei + NE;

    int *cnt, *ptr, *cursor, *csr;
    __nv_bfloat16 *xh, *xl, *z1h, *z1l, *h1h, *h1l, *hh, *hl, *z2h, *z2l;
    __nv_bfloat16 *w1ah, *w1al, *w1bh, *w1bl, *w2ah, *w2al;
    cudaGetSymbolAddress((void**)&cnt,    g_cnt);
    cudaGetSymbolAddress((void**)&ptr,    g_ptr);
    cudaGetSymbolAddress((void**)&cursor, g_cursor);
    cudaGetSymbolAddress((void**)&csr,    g_csr);
    cudaGetSymbolAddress((void**)&xh,     g_xh);
    cudaGetSymbolAddress((void**)&xl,     g_xl);
    cudaGetSymbolAddress((void**)&z1h,    g_z1h);
    cudaGetSymbolAddress((void**)&z1l,    g_z1l);
    cudaGetSymbolAddress((void**)&h1h,    g_h1h);
    cudaGetSymbolAddress((void**)&h1l,    g_h1l);
    cudaGetSymbolAddress((void**)&hh,     g_hh);
    cudaGetSymbolAddress((void**)&hl,     g_hl);
    cudaGetSymbolAddress((void**)&z2h,    g_z2h);
    cudaGetSymbolAddress((void**)&z2l,    g_z2l);
    cudaGetSymbolAddress((void**)&w1ah,   g_w1a_hi);
    cudaGetSymbolAddress((void**)&w1al,   g_w1a_lo);
    cudaGetSymbolAddress((void**)&w1bh,   g_w1b_hi);
    cudaGetSymbolAddress((void**)&w1bl,   g_w1b_lo);
    cudaGetSymbolAddress((void**)&w2ah,   g_w2a_hi);
    cudaGetSymbolAddress((void**)&w2al,   g_w2a_lo);

    cudaFuncSetAttribute(mma_gemm_kernel<false>,
                         cudaFuncAttributeMaxDynamicSharedMemorySize, SMTOT);
    cudaFuncSetAttribute(mma_gemm_kernel<true>,
                         cudaFuncAttributeMaxDynamicSharedMemorySize, SMTOT);

    const dim3 gemmGrid(2, (NN + 127) / 128);
    const int edgeGrid = (NE + 255) / 256;
    const int nodeGrid = (NN + 7) / 8;

    // ---- CSR build + split x (independent work first) ----
    cudaMemsetAsync(cnt, 0, sizeof(int) * NN);
    hist_kernel<<<edgeGrid, 256>>>(dst, cnt);
    pad_split_kernel<<<(NN * (KP1 / 4) + 255) / 256, 256>>>(x, xh, xl);
    scan_kernel<<<1, 1024>>>(cnt, ptr, cursor);
    fill_kernel<<<edgeGrid, 256>>>(src, dst, cursor, csr);

    // ---- weight prep ----
    prep_w_kernel<<<(HID * KP1 + 255) / 256, 256>>>(W1a, w1ah, w1al, INC, HID, KP1);
    prep_w_kernel<<<(HID * HID + 255) / 256, 256>>>(W1b, w1bh, w1bl, HID, HID, HID);
    prep_w_kernel<<<(HID * HID + 255) / 256, 256>>>(W2a, w2ah, w2al, HID, HID, HID);

    // ---- layer 1 ----
    gather_kernel<KP1 / 8><<<nodeGrid, 256>>>(
        (const uint4*)xh, (const uint4*)xl, ptr, csr, (uint4*)z1h, (uint4*)z1l);
    mma_gemm_kernel<false><<<gemmGrid, 256, SMTOT>>>(
        z1h, z1l, KP1, w1ah, w1al, KP1, b1a, h1h, h1l, nullptr, NN, nullptr);
    mma_gemm_kernel<false><<<gemmGrid, 256, SMTOT>>>(
        h1h, h1l, HID, w1bh, w1bl, HID, b1b, hh, hl, nullptr, NN, nullptr);

    // ---- layer 2 ----
    gather_kernel<HID / 8><<<nodeGrid, 256>>>(
        (const uint4*)hh, (const uint4*)hl, ptr, csr, (uint4*)z2h, (uint4*)z2l);
    init_out_kernel<<<(NN * 2 + 255) / 256, 256>>>(out, b2b);
    mma_gemm_kernel<true><<<gemmGrid, 256, SMTOT>>>(
        z2h, z2l, HID, w2ah, w2al, HID, b2a, nullptr, nullptr, out, NN, W2b);
}

// round 8
// speedup vs baseline: 1.0467x; 1.0467x over previous
#include <cuda_runtime.h>
#include <cuda_bf16.h>
#include <cstdint>

#define NN 50000
#define NE 800000
#define INC 165
#define HID 256
#define KP1 192              // K=165 padded to multiple of 64

// ---------------- scratch (no runtime allocation allowed) ----------------
__device__ int   g_cnt[NN];
__device__ int   g_ptr[NN + 1];
__device__ int   g_cursor[NN];
__device__ int   g_csr[NE];
__device__ __nv_bfloat16 g_xh[(size_t)NN * KP1];
__device__ __nv_bfloat16 g_xl[(size_t)NN * KP1];
__device__ __nv_bfloat16 g_z1h[(size_t)NN * KP1];
__device__ __nv_bfloat16 g_z1l[(size_t)NN * KP1];
__device__ __nv_bfloat16 g_h1h[(size_t)NN * HID];
__device__ __nv_bfloat16 g_h1l[(size_t)NN * HID];
__device__ __nv_bfloat16 g_hh[(size_t)NN * HID];
__device__ __nv_bfloat16 g_hl[(size_t)NN * HID];
__device__ __nv_bfloat16 g_z2h[(size_t)NN * HID];
__device__ __nv_bfloat16 g_z2l[(size_t)NN * HID];
__device__ __nv_bfloat16 g_w1a_hi[HID * KP1];
__device__ __nv_bfloat16 g_w1a_lo[HID * KP1];
__device__ __nv_bfloat16 g_w1b_hi[HID * HID];
__device__ __nv_bfloat16 g_w1b_lo[HID * HID];
__device__ __nv_bfloat16 g_w2a_hi[HID * HID];
__device__ __nv_bfloat16 g_w2a_lo[HID * HID];

// ---------------- PTX helpers ----------------
__device__ __forceinline__ uint32_t smem_u32(const void* p) {
    uint32_t a;
    asm("{ .reg .u64 t; cvta.to.shared.u64 t, %1; cvt.u32.u64 %0, t; }" : "=r"(a) : "l"(p));
    return a;
}
__device__ __forceinline__ void ldm_x4(uint32_t* r, uint32_t addr) {
    asm volatile("ldmatrix.sync.aligned.m8n8.x4.shared.b16 {%0,%1,%2,%3}, [%4];"
        : "=r"(r[0]), "=r"(r[1]), "=r"(r[2]), "=r"(r[3]) : "r"(addr));
}
__device__ __forceinline__ void ldm_x2(uint32_t* r, uint32_t addr) {
    asm volatile("ldmatrix.sync.aligned.m8n8.x2.shared.b16 {%0,%1}, [%2];"
        : "=r"(r[0]), "=r"(r[1]) : "r"(addr));
}
__device__ __forceinline__ void mma_bf16(float* c, const uint32_t* a, const uint32_t* b) {
    asm volatile("mma.sync.aligned.m16n8k16.row.col.f32.bf16.bf16.f32 "
        "{%0,%1,%2,%3}, {%4,%5,%6,%7}, {%8,%9}, {%0,%1,%2,%3};"
        : "+f"(c[0]), "+f"(c[1]), "+f"(c[2]), "+f"(c[3])
        : "r"(a[0]), "r"(a[1]), "r"(a[2]), "r"(a[3]), "r"(b[0]), "r"(b[1]));
}
__device__ __forceinline__ void cp16(uint32_t dst, const void* src) {
    asm volatile("cp.async.ca.shared.global [%0], [%1], 16;" :: "r"(dst), "l"(src));
}
__device__ __forceinline__ uint32_t pack2(float v0, float v1) {
    __nv_bfloat162 h = __floats2bfloat162_rn(v0, v1);
    return *(uint32_t*)&h;
}
__device__ __forceinline__ void acc8(float* a, uint4 h, uint4 l) {
    const uint32_t hu[4] = {h.x, h.y, h.z, h.w}, lu[4] = {l.x, l.y, l.z, l.w};
#pragma unroll
    for (int q = 0; q < 4; q++) {
        float2 fh = __bfloat1622float2(*(const __nv_bfloat162*)&hu[q]);
        float2 fl = __bfloat1622float2(*(const __nv_bfloat162*)&lu[q]);
        a[2 * q]     += fh.x + fl.x;
        a[2 * q + 1] += fh.y + fl.y;
    }
}
__device__ __forceinline__ void split8(const float* a, uint4& h, uint4& l) {
    uint32_t hu[4], lu[4];
#pragma unroll
    for (int q = 0; q < 4; q++) {
        float v0 = a[2 * q], v1 = a[2 * q + 1];
        hu[q] = pack2(v0, v1);
        float f0 = __bfloat162float(__float2bfloat16(v0));
        float f1 = __bfloat162float(__float2bfloat16(v1));
        lu[q] = pack2(v0 - f0, v1 - f1);
    }
    h = make_uint4(hu[0], hu[1], hu[2], hu[3]);
    l = make_uint4(lu[0], lu[1], lu[2], lu[3]);
}

// ---------------------------------------------------------------------------
// CSR build
// ---------------------------------------------------------------------------
__global__ void hist_kernel(const int* __restrict__ dst, int* __restrict__ cnt) {
    int e = blockIdx.x * blockDim.x + threadIdx.x;
    if (e < NE) atomicAdd(&cnt[__ldg(dst + e)], 1);
}

__global__ void scan_kernel(const int* __restrict__ cnt,
                            int* __restrict__ ptr, int* __restrict__ cursor) {
    __shared__ int wsum[32];
    __shared__ int running;
    const int t = threadIdx.x;
    if (t == 0) running = 0;
    __syncthreads();
    for (int base = 0; base < NN; base += 1024) {
        int v = (base + t < NN) ? cnt[base + t] : 0;
        int x = v;
#pragma unroll
        for (int o = 1; o < 32; o <<= 1) {
            int y = __shfl_up_sync(0xffffffffu, x, o);
            if ((t & 31) >= o) x += y;
        }
        if ((t & 31) == 31) wsum[t >> 5] = x;
        __syncthreads();
        if (t < 32) {
            int w = wsum[t];
#pragma unroll
            for (int o = 1; o < 32; o <<= 1) {
                int y = __shfl_up_sync(0xffffffffu, w, o);
                if (t >= o) w += y;
            }
            wsum[t] = w;
        }
        __syncthreads();
        int excl = x - v + ((t >= 32) ? wsum[(t >> 5) - 1] : 0) + running;
        if (base + t < NN) { ptr[base + t] = excl; cursor[base + t] = excl; }
        __syncthreads();
        if (t == 0) running += wsum[31];
        __syncthreads();
    }
    if (t == 0) ptr[NN] = running;
}

__global__ void fill_kernel(const int* __restrict__ src, const int* __restrict__ dst,
                            int* __restrict__ cursor, int* __restrict__ csr) {
    int e = blockIdx.x * blockDim.x + threadIdx.x;
    if (e < NE) {
        int p = atomicAdd(&cursor[__ldg(dst + e)], 1);
        csr[p] = __ldg(src + e);
    }
}

// x [NN][165] fp32 -> planar bf16 hi/lo [NN][192], zero-padded
__global__ void pad_split_kernel(const float* __restrict__ x,
                                 __nv_bfloat16* __restrict__ xh,
                                 __nv_bfloat16* __restrict__ xl) {
    int i = blockIdx.x * blockDim.x + threadIdx.x;
    if (i >= NN * (KP1 / 4)) return;
    int n = i / (KP1 / 4), c = (i % (KP1 / 4)) * 4;
    float v[4];
#pragma unroll
    for (int q = 0; q < 4; q++) {
        int cc = c + q;
        v[q] = (cc < INC) ? __ldg(&x[(size_t)n * INC + cc]) : 0.f;
    }
    uint32_t h0 = pack2(v[0], v[1]), h1 = pack2(v[2], v[3]);
    float f0 = __bfloat162float(__float2bfloat16(v[0]));
    float f1 = __bfloat162float(__float2bfloat16(v[1]));
    float f2 = __bfloat162float(__float2bfloat16(v[2]));
    float f3 = __bfloat162float(__float2bfloat16(v[3]));
    uint32_t l0 = pack2(v[0] - f0, v[1] - f1), l1 = pack2(v[2] - f2, v[3] - f3);
    *(uint32_t*)(xh + (size_t)n * KP1 + c) = h0;
    *(uint32_t*)(xh + (size_t)n * KP1 + c + 2) = h1;
    *(uint32_t*)(xl + (size_t)n * KP1 + c) = l0;
    *(uint32_t*)(xl + (size_t)n * KP1 + c + 2) = l1;
}

// ---------------------------------------------------------------------------
// Gather-aggregate on planar bf16 hi/lo: z[n] = f[n] + sum_nbr f[nbr].
// Warp per node; lane covers 8 columns (one uint4 per plane).
// ---------------------------------------------------------------------------
template<int RU4>   // uint4s per row (24 for K=192, 32 for K=256)
__global__ void gather_kernel(const uint4* __restrict__ fh, const uint4* __restrict__ fl,
                              const int* __restrict__ ptr, const int* __restrict__ csr,
                              uint4* __restrict__ zh, uint4* __restrict__ zl) {
    int n = blockIdx.x * (blockDim.x >> 5) + (threadIdx.x >> 5);
    if (n >= NN) return;
    const int lane = threadIdx.x & 31;
    if (lane >= RU4) return;
    float a[8] = {0, 0, 0, 0, 0, 0, 0, 0};
    acc8(a, __ldg(fh + (size_t)n * RU4 + lane), __ldg(fl + (size_t)n * RU4 + lane));
    const int e0 = __ldg(ptr + n), e1 = __ldg(ptr + n + 1);
    int j = e0;
    for (; j + 1 < e1; j += 2) {
        const size_t b0 = (size_t)__ldg(csr + j) * RU4;
        const size_t b1 = (size_t)__ldg(csr + j + 1) * RU4;
        uint4 h0 = __ldg(fh + b0 + lane), l0 = __ldg(fl + b0 + lane);
        uint4 h1 = __ldg(fh + b1 + lane), l1 = __ldg(fl + b1 + lane);
        acc8(a, h0, l0);
        acc8(a, h1, l1);
    }
    if (j < e1) {
        const size_t b0 = (size_t)__ldg(csr + j) * RU4;
        acc8(a, __ldg(fh + b0 + lane), __ldg(fl + b0 + lane));
    }
    uint4 oh, ol;
    split8(a, oh, ol);
    zh[(size_t)n * RU4 + lane] = oh;
    zl[(size_t)n * RU4 + lane] = ol;
}

// ---------------------------------------------------------------------------
// Weight prep: W[K,N] fp32 -> W^T split bf16 hi/lo, [N][Kp], zero-padded.
// ---------------------------------------------------------------------------
__global__ void prep_w_kernel(const float* __restrict__ W,
                              __nv_bfloat16* __restrict__ hi,
                              __nv_bfloat16* __restrict__ lo,
                              int K, int N, int Kp) {
    int i = blockIdx.x * blockDim.x + threadIdx.x;
    if (i >= N * Kp) return;
    int n = i / Kp, k = i % Kp;
    float w = (k < K) ? __ldg(&W[(size_t)k * N + n]) : 0.f;
    __nv_bfloat16 h = __float2bfloat16(w);
    hi[i] = h;
    lo[i] = __float2bfloat16(w - __bfloat162float(h));
}

__global__ void init_out_kernel(float* __restrict__ out, const float* __restrict__ b2) {
    int i = blockIdx.x * blockDim.x + threadIdx.x;
    if (i < NN * 2) out[i] = __ldg(b2 + (i & 1));
}

// ---------------------------------------------------------------------------
// Single-stage cp.async warp-MMA bf16-split GEMM (occupancy >= 2 CTA/SM).
// CTA tile 128x128, 8 warps 4Mx2N, warp tile 32x64.
// Non-OUTP epilogue: relu(acc+bias) -> planar bf16 hi/lo outputs.
// OUTP: relu(acc+bias) projected on w2[256][2], atomicAdd into Cout[M][2].
// ---------------------------------------------------------------------------
#define SROW 72
#define SMAT (128 * SROW * 2)      // 18432 B per tile
#define OFF_AHI 0
#define OFF_ALO (SMAT)
#define OFF_BHI (2 * SMAT)
#define OFF_BLO (3 * SMAT)
#define SMTOT (4 * SMAT)           // 73728 B

template<bool OUTP>
__global__ __launch_bounds__(256, 2)
void mma_gemm_kernel(const __nv_bfloat16* __restrict__ Ah,
                     const __nv_bfloat16* __restrict__ Al, int lda,
                     const __nv_bfloat16* __restrict__ Bh,
                     const __nv_bfloat16* __restrict__ Bl, int Kp,
                     const float* __restrict__ bias,
                     __nv_bfloat16* __restrict__ Ch, __nv_bfloat16* __restrict__ Cl,
                     float* __restrict__ Cout, int M,
                     const float* __restrict__ w2) {
    extern __shared__ __align__(16) char smem[];
    const uint32_t sb = smem_u32(smem);
    const int tid = threadIdx.x, wid = tid >> 5, lane = tid & 31;

    const int bm0 = blockIdx.y * 128;
    const int n0 = blockIdx.x * 128;

    const int arow = tid >> 1;
    const int acol0 = (tid & 1) * 32;
    const int mw = (wid >> 1) * 32;
    const int nw = (wid & 1) * 64;

    // source row pointers for the loader (clamped; OOB rows discarded at store)
    const int gRow = bm0 + arow;
    const __nv_bfloat16* pAh = Ah + (size_t)(gRow < M ? gRow : 0) * lda + acol0;
    const __nv_bfloat16* pAl = Al + (size_t)(gRow < M ? gRow : 0) * lda + acol0;
    const __nv_bfloat16* pBh = Bh + (size_t)(n0 + arow) * Kp + acol0;
    const __nv_bfloat16* pBl = Bl + (size_t)(n0 + arow) * Kp + acol0;
    const uint32_t sdst = sb + (uint32_t)(arow * SROW + acol0) * 2;

    const int nchunks = Kp >> 6;

    float acc[2][8][4];
#pragma unroll
    for (int ms = 0; ms < 2; ms++)
#pragma unroll
        for (int ns = 0; ns < 8; ns++)
#pragma unroll
            for (int q = 0; q < 4; q++) acc[ms][ns][q] = 0.f;

    const int l7 = lane & 7;
    const int aRowAdd = ((lane >> 3) & 1) * 8;
    const int aKAdd = (lane >> 4) * 8;
    const int bl = lane & 15;
    const int bRow = bl & 7;
    const int bKAdd = ((bl >> 3) & 1) * 8;

    for (int ch = 0; ch < nchunks; ch++) {
        const int k0 = ch << 6;
#pragma unroll
        for (int q = 0; q < 4; q++) {
            cp16(sdst + OFF_AHI + q * 16, pAh + k0 + q * 8);
            cp16(sdst + OFF_ALO + q * 16, pAl + k0 + q * 8);
            cp16(sdst + OFF_BHI + q * 16, pBh + k0 + q * 8);
            cp16(sdst + OFF_BLO + q * 16, pBl + k0 + q * 8);
        }
        asm volatile("cp.async.commit_group;" ::: "memory");
        asm volatile("cp.async.wait_group 0;" ::: "memory");
        __syncthreads();

#pragma unroll
        for (int kk = 0; kk < 64; kk += 16) {
            uint32_t ahi[2][4], alo[2][4], bhi[8][2], blo[8][2];
#pragma unroll
            for (int ms = 0; ms < 2; ms++) {
                uint32_t ra = sb + (uint32_t)((mw + ms * 16 + l7 + aRowAdd) * SROW + kk + aKAdd) * 2;
                ldm_x4(ahi[ms], ra + OFF_AHI);
                ldm_x4(alo[ms], ra + OFF_ALO);
            }
#pragma unroll
            for (int ns = 0; ns < 8; ns++) {
                uint32_t rb = sb + (uint32_t)((nw + ns * 8 + bRow) * SROW + kk + bKAdd) * 2;
                ldm_x2(bhi[ns], rb + OFF_BHI);
                ldm_x2(blo[ns], rb + OFF_BLO);
            }
#pragma unroll
            for (int ms = 0; ms < 2; ms++)
#pragma unroll
                for (int ns = 0; ns < 8; ns++) {
                    mma_bf16(acc[ms][ns], ahi[ms], bhi[ns]);
                    mma_bf16(acc[ms][ns], alo[ms], bhi[ns]);
                    mma_bf16(acc[ms][ns], ahi[ms], blo[ns]);
                }
        }
        __syncthreads();
    }

    const int r = lane >> 2;
    const int cp = (lane & 3) * 2;

    if (OUTP) {
        float s[2][2][2];
#pragma unroll
        for (int ms = 0; ms < 2; ms++)
#pragma unroll
            for (int rh = 0; rh < 2; rh++) { s[ms][rh][0] = 0.f; s[ms][rh][1] = 0.f; }
#pragma unroll
        for (int ms = 0; ms < 2; ms++)
#pragma unroll
            for (int ns = 0; ns < 8; ns++) {
                const int col = n0 + nw + ns * 8 + cp;
                const float2 bb = *(const float2*)(bias + col);
                const float2 w0 = *(const float2*)(w2 + col * 2);
                const float2 w1 = *(const float2*)(w2 + (col + 1) * 2);
                float v0 = fmaxf(acc[ms][ns][0] + bb.x, 0.f);
                float v1 = fmaxf(acc[ms][ns][1] + bb.y, 0.f);
                float v2 = fmaxf(acc[ms][ns][2] + bb.x, 0.f);
                float v3 = fmaxf(acc[ms][ns][3] + bb.y, 0.f);
                s[ms][0][0] += v0 * w0.x + v1 * w1.x;
                s[ms][0][1] += v0 * w0.y + v1 * w1.y;
                s[ms][1][0] += v2 * w0.x + v3 * w1.x;
                s[ms][1][1] += v2 * w0.y + v3 * w1.y;
            }
#pragma unroll
        for (int ms = 0; ms < 2; ms++)
#pragma unroll
            for (int rh = 0; rh < 2; rh++)
#pragma unroll
                for (int oc = 0; oc < 2; oc++) {
                    float v = s[ms][rh][oc];
                    v += __shfl_xor_sync(0xffffffffu, v, 1);
                    v += __shfl_xor_sync(0xffffffffu, v, 2);
                    s[ms][rh][oc] = v;
                }
        if ((lane & 3) == 0) {
#pragma unroll
            for (int ms = 0; ms < 2; ms++)
#pragma unroll
                for (int rh = 0; rh < 2; rh++) {
                    const int row = bm0 + mw + ms * 16 + r + rh * 8;
                    if (row < M) {
                        atomicAdd(Cout + (size_t)row * 2 + 0, s[ms][rh][0]);
                        atomicAdd(Cout + (size_t)row * 2 + 1, s[ms][rh][1]);
                    }
                }
        }
    } else {
#pragma unroll
        for (int ms = 0; ms < 2; ms++)
#pragma unroll
            for (int ns = 0; ns < 8; ns++) {
                const int col = n0 + nw + ns * 8 + cp;
                const float2 bb = *(const float2*)(bias + col);
                const int row0 = bm0 + mw + ms * 16 + r;
                float v0 = fmaxf(acc[ms][ns][0] + bb.x, 0.f);
                float v1 = fmaxf(acc[ms][ns][1] + bb.y, 0.f);
                float v2 = fmaxf(acc[ms][ns][2] + bb.x, 0.f);
                float v3 = fmaxf(acc[ms][ns][3] + bb.y, 0.f);
#pragma unroll
                for (int rh = 0; rh < 2; rh++) {
                    const int row = row0 + rh * 8;
                    if (row >= M) continue;
                    float a0 = rh ? v2 : v0, a1 = rh ? v3 : v1;
                    uint32_t hp = pack2(a0, a1);
                    float f0 = __bfloat162float(__float2bfloat16(a0));
                    float f1 = __bfloat162float(__float2bfloat16(a1));
                    uint32_t lp = pack2(a0 - f0, a1 - f1);
                    *(uint32_t*)(Ch + (size_t)row * HID + col) = hp;
                    *(uint32_t*)(Cl + (size_t)row * HID + col) = lp;
                }
            }
    }
}

// ---------------------------------------------------------------------------
extern "C" void kernel_launch(void* const* d_in, const int* in_sizes, int n_in,
                              void* d_out, int out_size) {
    const float* x   = (const float*)d_in[0];
    const int*   ei  = (const int*)d_in[1];
    const float* W1a = (const float*)d_in[2];
    const float* b1a = (const float*)d_in[3];
    const float* W1b = (const float*)d_in[4];
    const float* b1b = (const float*)d_in[5];
    const float* W2a = (const float*)d_in[6];
    const float* b2a = (const float*)d_in[7];
    const float* W2b = (const float*)d_in[8];
    const float* b2b = (const float*)d_in[9];
    float* out = (float*)d_out;

    const int* src = ei;
    const int* dst = ei + NE;

    int *cnt, *ptr, *cursor, *csr;
    __nv_bfloat16 *xh, *xl, *z1h, *z1l, *h1h, *h1l, *hh, *hl, *z2h, *z2l;
    __nv_bfloat16 *w1ah, *w1al, *w1bh, *w1bl, *w2ah, *w2al;
    cudaGetSymbolAddress((void**)&cnt,    g_cnt);
    cudaGetSymbolAddress((void**)&ptr,    g_ptr);
    cudaGetSymbolAddress((void**)&cursor, g_cursor);
    cudaGetSymbolAddress((void**)&csr,    g_csr);
    cudaGetSymbolAddress((void**)&xh,     g_xh);
    cudaGetSymbolAddress((void**)&xl,     g_xl);
    cudaGetSymbolAddress((void**)&z1h,    g_z1h);
    cudaGetSymbolAddress((void**)&z1l,    g_z1l);
    cudaGetSymbolAddress((void**)&h1h,    g_h1h);
    cudaGetSymbolAddress((void**)&h1l,    g_h1l);
    cudaGetSymbolAddress((void**)&hh,     g_hh);
    cudaGetSymbolAddress((void**)&hl,     g_hl);
    cudaGetSymbolAddress((void**)&z2h,    g_z2h);
    cudaGetSymbolAddress((void**)&z2l,    g_z2l);
    cudaGetSymbolAddress((void**)&w1ah,   g_w1a_hi);
    cudaGetSymbolAddress((void**)&w1al,   g_w1a_lo);
    cudaGetSymbolAddress((void**)&w1bh,   g_w1b_hi);
    cudaGetSymbolAddress((void**)&w1bl,   g_w1b_lo);
    cudaGetSymbolAddress((void**)&w2ah,   g_w2a_hi);
    cudaGetSymbolAddress((void**)&w2al,   g_w2a_lo);

    cudaFuncSetAttribute(mma_gemm_kernel<false>,
                         cudaFuncAttributeMaxDynamicSharedMemorySize, SMTOT);
    cudaFuncSetAttribute(mma_gemm_kernel<true>,
                         cudaFuncAttributeMaxDynamicSharedMemorySize, SMTOT);

    const dim3 gemmGrid(2, (NN + 127) / 128);
    const int edgeGrid = (NE + 255) / 256;
    const int nodeGrid = (NN + 7) / 8;

    // ---- CSR build + split x (independent work first) ----
    cudaMemsetAsync(cnt, 0, sizeof(int) * NN);
    hist_kernel<<<edgeGrid, 256>>>(dst, cnt);
    pad_split_kernel<<<(NN * (KP1 / 4) + 255) / 256, 256>>>(x, xh, xl);
    scan_kernel<<<1, 1024>>>(cnt, ptr, cursor);
    fill_kernel<<<edgeGrid, 256>>>(src, dst, cursor, csr);

    // ---- weight prep ----
    prep_w_kernel<<<(HID * KP1 + 255) / 256, 256>>>(W1a, w1ah, w1al, INC, HID, KP1);
    prep_w_kernel<<<(HID * HID + 255) / 256, 256>>>(W1b, w1bh, w1bl, HID, HID, HID);
    prep_w_kernel<<<(HID * HID + 255) / 256, 256>>>(W2a, w2ah, w2al, HID, HID, HID);

    // ---- layer 1 ----
    gather_kernel<KP1 / 8><<<nodeGrid, 256>>>(
        (const uint4*)xh, (const uint4*)xl, ptr, csr, (uint4*)z1h, (uint4*)z1l);
    mma_gemm_kernel<false><<<gemmGrid, 256, SMTOT>>>(
        z1h, z1l, KP1, w1ah, w1al, KP1, b1a, h1h, h1l, nullptr, NN, nullptr);
    mma_gemm_kernel<false><<<gemmGrid, 256, SMTOT>>>(
        h1h, h1l, HID, w1bh, w1bl, HID, b1b, hh, hl, nullptr, NN, nullptr);

    // ---- layer 2 ----
    gather_kernel<HID / 8><<<nodeGrid, 256>>>(
        (const uint4*)hh, (const uint4*)hl, ptr, csr, (uint4*)z2h, (uint4*)z2l);
    init_out_kernel<<<(NN * 2 + 255) / 256, 256>>>(out, b2b);
    mma_gemm_kernel<true><<<gemmGrid, 256, SMTOT>>>(
        z2h, z2l, HID, w2ah, w2al, HID, b2a, nullptr, nullptr, out, NN, W2b);
}

// round 9
// speedup vs baseline: 1.2507x; 1.1948x over previous
#include <cuda_runtime.h>
#include <cuda_fp16.h>
#include <cstdint>

#define NN 50000
#define NE 800000
#define INC 165
#define HID 256
#define KP1 192              // K=165 padded to multiple of 64

// ---------------- scratch (no runtime allocation allowed) ----------------
__device__ int   g_cnt[NN];
__device__ int   g_ptr[NN + 1];
__device__ int   g_cursor[NN];
__device__ int   g_csr[NE];
__device__ __half g_xh[(size_t)NN * KP1];
__device__ __half g_xl[(size_t)NN * KP1];
__device__ __half g_z1h[(size_t)NN * KP1];
__device__ __half g_z1l[(size_t)NN * KP1];
__device__ __half g_h1h[(size_t)NN * HID];
__device__ __half g_h1l[(size_t)NN * HID];
__device__ __half g_hh[(size_t)NN * HID];
__device__ __half g_hl[(size_t)NN * HID];
__device__ __half g_z2h[(size_t)NN * HID];
__device__ __half g_z2l[(size_t)NN * HID];
__device__ __half g_w1a[HID * KP1];
__device__ __half g_w1b[HID * HID];
__device__ __half g_w2a[HID * HID];

// ---------------- PTX helpers ----------------
__device__ __forceinline__ uint32_t smem_u32(const void* p) {
    uint32_t a;
    asm("{ .reg .u64 t; cvta.to.shared.u64 t, %1; cvt.u32.u64 %0, t; }" : "=r"(a) : "l"(p));
    return a;
}
__device__ __forceinline__ void ldm_x4(uint32_t* r, uint32_t addr) {
    asm volatile("ldmatrix.sync.aligned.m8n8.x4.shared.b16 {%0,%1,%2,%3}, [%4];"
        : "=r"(r[0]), "=r"(r[1]), "=r"(r[2]), "=r"(r[3]) : "r"(addr));
}
__device__ __forceinline__ void ldm_x2(uint32_t* r, uint32_t addr) {
    asm volatile("ldmatrix.sync.aligned.m8n8.x2.shared.b16 {%0,%1}, [%2];"
        : "=r"(r[0]), "=r"(r[1]) : "r"(addr));
}
__device__ __forceinline__ void mma_f16(float* c, const uint32_t* a, const uint32_t* b) {
    asm volatile("mma.sync.aligned.m16n8k16.row.col.f32.f16.f16.f32 "
        "{%0,%1,%2,%3}, {%4,%5,%6,%7}, {%8,%9}, {%0,%1,%2,%3};"
        : "+f"(c[0]), "+f"(c[1]), "+f"(c[2]), "+f"(c[3])
        : "r"(a[0]), "r"(a[1]), "r"(a[2]), "r"(a[3]), "r"(b[0]), "r"(b[1]));
}
__device__ __forceinline__ void cp16(uint32_t dst, const void* src) {
    asm volatile("cp.async.ca.shared.global [%0], [%1], 16;" :: "r"(dst), "l"(src));
}
__device__ __forceinline__ uint32_t pack2h(float v0, float v1) {
    __half2 h = __floats2half2_rn(v0, v1);   // x = v0 (low), y = v1 (high)
    return *(uint32_t*)&h;
}
__device__ __forceinline__ void acc8(float* a, uint4 h, uint4 l) {
    const uint32_t hu[4] = {h.x, h.y, h.z, h.w}, lu[4] = {l.x, l.y, l.z, l.w};
#pragma unroll
    for (int q = 0; q < 4; q++) {
        float2 fh = __half22float2(*(const __half2*)&hu[q]);
        float2 fl = __half22float2(*(const __half2*)&lu[q]);
        a[2 * q]     += fh.x + fl.x;
        a[2 * q + 1] += fh.y + fl.y;
    }
}
__device__ __forceinline__ void split8(const float* a, uint4& h, uint4& l) {
    uint32_t hu[4], lu[4];
#pragma unroll
    for (int q = 0; q < 4; q++) {
        float v0 = a[2 * q], v1 = a[2 * q + 1];
        hu[q] = pack2h(v0, v1);
        float f0 = __half2float(__float2half_rn(v0));
        float f1 = __half2float(__float2half_rn(v1));
        lu[q] = pack2h(v0 - f0, v1 - f1);
    }
    h = make_uint4(hu[0], hu[1], hu[2], hu[3]);
    l = make_uint4(lu[0], lu[1], lu[2], lu[3]);
}

// ---------------------------------------------------------------------------
// CSR build
// ---------------------------------------------------------------------------
__global__ void hist_kernel(const int* __restrict__ dst, int* __restrict__ cnt) {
    int e = blockIdx.x * blockDim.x + threadIdx.x;
    if (e < NE) atomicAdd(&cnt[__ldg(dst + e)], 1);
}

__global__ void scan_kernel(const int* __restrict__ cnt,
                            int* __restrict__ ptr, int* __restrict__ cursor) {
    __shared__ int wsum[32];
    __shared__ int running;
    const int t = threadIdx.x;
    if (t == 0) running = 0;
    __syncthreads();
    for (int base = 0; base < NN; base += 1024) {
        int v = (base + t < NN) ? cnt[base + t] : 0;
        int x = v;
#pragma unroll
        for (int o = 1; o < 32; o <<= 1) {
            int y = __shfl_up_sync(0xffffffffu, x, o);
            if ((t & 31) >= o) x += y;
        }
        if ((t & 31) == 31) wsum[t >> 5] = x;
        __syncthreads();
        if (t < 32) {
            int w = wsum[t];
#pragma unroll
            for (int o = 1; o < 32; o <<= 1) {
                int y = __shfl_up_sync(0xffffffffu, w, o);
                if (t >= o) w += y;
            }
            wsum[t] = w;
        }
        __syncthreads();
        int excl = x - v + ((t >= 32) ? wsum[(t >> 5) - 1] : 0) + running;
        if (base + t < NN) { ptr[base + t] = excl; cursor[base + t] = excl; }
        __syncthreads();
        if (t == 0) running += wsum[31];
        __syncthreads();
    }
    if (t == 0) ptr[NN] = running;
}

__global__ void fill_kernel(const int* __restrict__ src, const int* __restrict__ dst,
                            int* __restrict__ cursor, int* __restrict__ csr) {
    int e = blockIdx.x * blockDim.x + threadIdx.x;
    if (e < NE) {
        int p = atomicAdd(&cursor[__ldg(dst + e)], 1);
        csr[p] = __ldg(src + e);
    }
}

// x [NN][165] fp32 -> planar fp16 hi/lo [NN][192], zero-padded
__global__ void pad_split_kernel(const float* __restrict__ x,
                                 __half* __restrict__ xh,
                                 __half* __restrict__ xl) {
    int i = blockIdx.x * blockDim.x + threadIdx.x;
    if (i >= NN * (KP1 / 4)) return;
    int n = i / (KP1 / 4), c = (i % (KP1 / 4)) * 4;
    float v[4];
#pragma unroll
    for (int q = 0; q < 4; q++) {
        int cc = c + q;
        v[q] = (cc < INC) ? __ldg(&x[(size_t)n * INC + cc]) : 0.f;
    }
    uint32_t h0 = pack2h(v[0], v[1]), h1 = pack2h(v[2], v[3]);
    float f0 = __half2float(__float2half_rn(v[0]));
    float f1 = __half2float(__float2half_rn(v[1]));
    float f2 = __half2float(__float2half_rn(v[2]));
    float f3 = __half2float(__float2half_rn(v[3]));
    uint32_t l0 = pack2h(v[0] - f0, v[1] - f1), l1 = pack2h(v[2] - f2, v[3] - f3);
    *(uint32_t*)(xh + (size_t)n * KP1 + c) = h0;
    *(uint32_t*)(xh + (size_t)n * KP1 + c + 2) = h1;
    *(uint32_t*)(xl + (size_t)n * KP1 + c) = l0;
    *(uint32_t*)(xl + (size_t)n * KP1 + c + 2) = l1;
}

// ---------------------------------------------------------------------------
// Gather-aggregate on planar fp16 hi/lo: z[n] = f[n] + sum_nbr f[nbr].
// Warp per node; lane covers 8 columns (one uint4 per plane).
// ---------------------------------------------------------------------------
template<int RU4>   // uint4s per row (24 for K=192, 32 for K=256)
__global__ void gather_kernel(const uint4* __restrict__ fh, const uint4* __restrict__ fl,
                              const int* __restrict__ ptr, const int* __restrict__ csr,
                              uint4* __restrict__ zh, uint4* __restrict__ zl) {
    int n = blockIdx.x * (blockDim.x >> 5) + (threadIdx.x >> 5);
    if (n >= NN) return;
    const int lane = threadIdx.x & 31;
    if (lane >= RU4) return;
    float a[8] = {0, 0, 0, 0, 0, 0, 0, 0};
    acc8(a, __ldg(fh + (size_t)n * RU4 + lane), __ldg(fl + (size_t)n * RU4 + lane));
    const int e0 = __ldg(ptr + n), e1 = __ldg(ptr + n + 1);
    int j = e0;
    for (; j + 1 < e1; j += 2) {
        const size_t b0 = (size_t)__ldg(csr + j) * RU4;
        const size_t b1 = (size_t)__ldg(csr + j + 1) * RU4;
        uint4 h0 = __ldg(fh + b0 + lane), l0 = __ldg(fl + b0 + lane);
        uint4 h1 = __ldg(fh + b1 + lane), l1 = __ldg(fl + b1 + lane);
        acc8(a, h0, l0);
        acc8(a, h1, l1);
    }
    if (j < e1) {
        const size_t b0 = (size_t)__ldg(csr + j) * RU4;
        acc8(a, __ldg(fh + b0 + lane), __ldg(fl + b0 + lane));
    }
    uint4 oh, ol;
    split8(a, oh, ol);
    zh[(size_t)n * RU4 + lane] = oh;
    zl[(size_t)n * RU4 + lane] = ol;
}

// ---------------------------------------------------------------------------
// Weight prep: W[K,N] fp32 -> W^T fp16 (single plane), [N][Kp], zero-padded.
// ---------------------------------------------------------------------------
__global__ void prep_w_kernel(const float* __restrict__ W,
                              __half* __restrict__ hi,
                              int K, int N, int Kp) {
    int i = blockIdx.x * blockDim.x + threadIdx.x;
    if (i >= N * Kp) return;
    int n = i / Kp, k = i % Kp;
    float w = (k < K) ? __ldg(&W[(size_t)k * N + n]) : 0.f;
    hi[i] = __float2half_rn(w);
}

__global__ void init_out_kernel(float* __restrict__ out, const float* __restrict__ b2) {
    int i = blockIdx.x * blockDim.x + threadIdx.x;
    if (i < NN * 2) out[i] = __ldg(b2 + (i & 1));
}

// ---------------------------------------------------------------------------
// Single-stage cp.async warp-MMA fp16 2-term split GEMM (>=2 CTA/SM).
// C = (Ahi + Alo) @ Bhi : 2 MMAs per fragment pair instead of 3.
// CTA tile 128x128, 8 warps 4Mx2N, warp tile 32x64.
// Non-OUTP epilogue: relu(acc+bias) -> planar fp16 hi/lo outputs.
// OUTP: relu(acc+bias) projected on w2[256][2], atomicAdd into Cout[M][2].
// ---------------------------------------------------------------------------
#define SROW 72
#define SMAT (128 * SROW * 2)      // 18432 B per tile
#define OFF_AHI 0
#define OFF_ALO (SMAT)
#define OFF_BHI (2 * SMAT)
#define SMTOT (3 * SMAT)           // 55296 B

template<bool OUTP>
__global__ __launch_bounds__(256, 2)
void mma_gemm_kernel(const __half* __restrict__ Ah,
                     const __half* __restrict__ Al, int lda,
                     const __half* __restrict__ Bh, int Kp,
                     const float* __restrict__ bias,
                     __half* __restrict__ Ch, __half* __restrict__ Cl,
                     float* __restrict__ Cout, int M,
                     const float* __restrict__ w2) {
    extern __shared__ __align__(16) char smem[];
    const uint32_t sb = smem_u32(smem);
    const int tid = threadIdx.x, wid = tid >> 5, lane = tid & 31;

    const int bm0 = blockIdx.y * 128;
    const int n0 = blockIdx.x * 128;

    const int arow = tid >> 1;
    const int acol0 = (tid & 1) * 32;
    const int mw = (wid >> 1) * 32;
    const int nw = (wid & 1) * 64;

    // source row pointers for the loader (clamped; OOB rows discarded at store)
    const int gRow = bm0 + arow;
    const __half* pAh = Ah + (size_t)(gRow < M ? gRow : 0) * lda + acol0;
    const __half* pAl = Al + (size_t)(gRow < M ? gRow : 0) * lda + acol0;
    const __half* pBh = Bh + (size_t)(n0 + arow) * Kp + acol0;
    const uint32_t sdst = sb + (uint32_t)(arow * SROW + acol0) * 2;

    const int nchunks = Kp >> 6;

    float acc[2][8][4];
#pragma unroll
    for (int ms = 0; ms < 2; ms++)
#pragma unroll
        for (int ns = 0; ns < 8; ns++)
#pragma unroll
            for (int q = 0; q < 4; q++) acc[ms][ns][q] = 0.f;

    const int l7 = lane & 7;
    const int aRowAdd = ((lane >> 3) & 1) * 8;
    const int aKAdd = (lane >> 4) * 8;
    const int bl = lane & 15;
    const int bRow = bl & 7;
    const int bKAdd = ((bl >> 3) & 1) * 8;

    for (int ch = 0; ch < nchunks; ch++) {
        const int k0 = ch << 6;
#pragma unroll
        for (int q = 0; q < 4; q++) {
            cp16(sdst + OFF_AHI + q * 16, pAh + k0 + q * 8);
            cp16(sdst + OFF_ALO + q * 16, pAl + k0 + q * 8);
            cp16(sdst + OFF_BHI + q * 16, pBh + k0 + q * 8);
        }
        asm volatile("cp.async.commit_group;" ::: "memory");
        asm volatile("cp.async.wait_group 0;" ::: "memory");
        __syncthreads();

#pragma unroll
        for (int kk = 0; kk < 64; kk += 16) {
            uint32_t ahi[2][4], alo[2][4], bhi[8][2];
#pragma unroll
            for (int ms = 0; ms < 2; ms++) {
                uint32_t ra = sb + (uint32_t)((mw + ms * 16 + l7 + aRowAdd) * SROW + kk + aKAdd) * 2;
                ldm_x4(ahi[ms], ra + OFF_AHI);
                ldm_x4(alo[ms], ra + OFF_ALO);
            }
#pragma unroll
            for (int ns = 0; ns < 8; ns++) {
                uint32_t rb = sb + (uint32_t)((nw + ns * 8 + bRow) * SROW + kk + bKAdd) * 2;
                ldm_x2(bhi[ns], rb + OFF_BHI);
            }
#pragma unroll
            for (int ms = 0; ms < 2; ms++)
#pragma unroll
                for (int ns = 0; ns < 8; ns++) {
                    mma_f16(acc[ms][ns], ahi[ms], bhi[ns]);
                    mma_f16(acc[ms][ns], alo[ms], bhi[ns]);
                }
        }
        __syncthreads();
    }

    const int r = lane >> 2;
    const int cp = (lane & 3) * 2;

    if (OUTP) {
        float s[2][2][2];
#pragma unroll
        for (int ms = 0; ms < 2; ms++)
#pragma unroll
            for (int rh = 0; rh < 2; rh++) { s[ms][rh][0] = 0.f; s[ms][rh][1] = 0.f; }
#pragma unroll
        for (int ms = 0; ms < 2; ms++)
#pragma unroll
            for (int ns = 0; ns < 8; ns++) {
                const int col = n0 + nw + ns * 8 + cp;
                const float2 bb = *(const float2*)(bias + col);
                const float2 w0 = *(const float2*)(w2 + col * 2);
                const float2 w1 = *(const float2*)(w2 + (col + 1) * 2);
                float v0 = fmaxf(acc[ms][ns][0] + bb.x, 0.f);
                float v1 = fmaxf(acc[ms][ns][1] + bb.y, 0.f);
                float v2 = fmaxf(acc[ms][ns][2] + bb.x, 0.f);
                float v3 = fmaxf(acc[ms][ns][3] + bb.y, 0.f);
                s[ms][0][0] += v0 * w0.x + v1 * w1.x;
                s[ms][0][1] += v0 * w0.y + v1 * w1.y;
                s[ms][1][0] += v2 * w0.x + v3 * w1.x;
                s[ms][1][1] += v2 * w0.y + v3 * w1.y;
            }
#pragma unroll
        for (int ms = 0; ms < 2; ms++)
#pragma unroll
            for (int rh = 0; rh < 2; rh++)
#pragma unroll
                for (int oc = 0; oc < 2; oc++) {
                    float v = s[ms][rh][oc];
                    v += __shfl_xor_sync(0xffffffffu, v, 1);
                    v += __shfl_xor_sync(0xffffffffu, v, 2);
                    s[ms][rh][oc] = v;
                }
        if ((lane & 3) == 0) {
#pragma unroll
            for (int ms = 0; ms < 2; ms++)
#pragma unroll
                for (int rh = 0; rh < 2; rh++) {
                    const int row = bm0 + mw + ms * 16 + r + rh * 8;
                    if (row < M) {
                        atomicAdd(Cout + (size_t)row * 2 + 0, s[ms][rh][0]);
                        atomicAdd(Cout + (size_t)row * 2 + 1, s[ms][rh][1]);
                    }
                }
        }
    } else {
#pragma unroll
        for (int ms = 0; ms < 2; ms++)
#pragma unroll
            for (int ns = 0; ns < 8; ns++) {
                const int col = n0 + nw + ns * 8 + cp;
                const float2 bb = *(const float2*)(bias + col);
                const int row0 = bm0 + mw + ms * 16 + r;
                float v0 = fmaxf(acc[ms][ns][0] + bb.x, 0.f);
                float v1 = fmaxf(acc[ms][ns][1] + bb.y, 0.f);
                float v2 = fmaxf(acc[ms][ns][2] + bb.x, 0.f);
                float v3 = fmaxf(acc[ms][ns][3] + bb.y, 0.f);
#pragma unroll
                for (int rh = 0; rh < 2; rh++) {
                    const int row = row0 + rh * 8;
                    if (row >= M) continue;
                    float a0 = rh ? v2 : v0, a1 = rh ? v3 : v1;
                    uint32_t hp = pack2h(a0, a1);
                    float f0 = __half2float(__float2half_rn(a0));
                    float f1 = __half2float(__float2half_rn(a1));
                    uint32_t lp = pack2h(a0 - f0, a1 - f1);
                    *(uint32_t*)(Ch + (size_t)row * HID + col) = hp;
                    *(uint32_t*)(Cl + (size_t)row * HID + col) = lp;
                }
            }
    }
}

// ---------------------------------------------------------------------------
extern "C" void kernel_launch(void* const* d_in, const int* in_sizes, int n_in,
                              void* d_out, int out_size) {
    const float* x   = (const float*)d_in[0];
    const int*   ei  = (const int*)d_in[1];
    const float* W1a = (const float*)d_in[2];
    const float* b1a = (const float*)d_in[3];
    const float* W1b = (const float*)d_in[4];
    const float* b1b = (const float*)d_in[5];
    const float* W2a = (const float*)d_in[6];
    const float* b2a = (const float*)d_in[7];
    const float* W2b = (const float*)d_in[8];
    const float* b2b = (const float*)d_in[9];
    float* out = (float*)d_out;

    const int* src = ei;
    const int* dst = ei + NE;

    int *cnt, *ptr, *cursor, *csr;
    __half *xh, *xl, *z1h, *z1l, *h1h, *h1l, *hh, *hl, *z2h, *z2l;
    __half *w1a, *w1b, *w2a;
    cudaGetSymbolAddress((void**)&cnt,    g_cnt);
    cudaGetSymbolAddress((void**)&ptr,    g_ptr);
    cudaGetSymbolAddress((void**)&cursor, g_cursor);
    cudaGetSymbolAddress((void**)&csr,    g_csr);
    cudaGetSymbolAddress((void**)&xh,     g_xh);
    cudaGetSymbolAddress((void**)&xl,     g_xl);
    cudaGetSymbolAddress((void**)&z1h,    g_z1h);
    cudaGetSymbolAddress((void**)&z1l,    g_z1l);
    cudaGetSymbolAddress((void**)&h1h,    g_h1h);
    cudaGetSymbolAddress((void**)&h1l,    g_h1l);
    cudaGetSymbolAddress((void**)&hh,     g_hh);
    cudaGetSymbolAddress((void**)&hl,     g_hl);
    cudaGetSymbolAddress((void**)&z2h,    g_z2h);
    cudaGetSymbolAddress((void**)&z2l,    g_z2l);
    cudaGetSymbolAddress((void**)&w1a,    g_w1a);
    cudaGetSymbolAddress((void**)&w1b,    g_w1b);
    cudaGetSymbolAddress((void**)&w2a,    g_w2a);

    cudaFuncSetAttribute(mma_gemm_kernel<false>,
                         cudaFuncAttributeMaxDynamicSharedMemorySize, SMTOT);
    cudaFuncSetAttribute(mma_gemm_kernel<true>,
                         cudaFuncAttributeMaxDynamicSharedMemorySize, SMTOT);

    const dim3 gemmGrid(2, (NN + 127) / 128);
    const int edgeGrid = (NE + 255) / 256;
    const int nodeGrid = (NN + 7) / 8;

    // ---- CSR build + split x (independent work first) ----
    cudaMemsetAsync(cnt, 0, sizeof(int) * NN);
    hist_kernel<<<edgeGrid, 256>>>(dst, cnt);
    pad_split_kernel<<<(NN * (KP1 / 4) + 255) / 256, 256>>>(x, xh, xl);
    scan_kernel<<<1, 1024>>>(cnt, ptr, cursor);
    fill_kernel<<<edgeGrid, 256>>>(src, dst, cursor, csr);

    // ---- weight prep (single fp16 plane) ----
    prep_w_kernel<<<(HID * KP1 + 255) / 256, 256>>>(W1a, w1a, INC, HID, KP1);
    prep_w_kernel<<<(HID * HID + 255) / 256, 256>>>(W1b, w1b, HID, HID, HID);
    prep_w_kernel<<<(HID * HID + 255) / 256, 256>>>(W2a, w2a, HID, HID, HID);

    // ---- layer 1 ----
    gather_kernel<KP1 / 8><<<nodeGrid, 256>>>(
        (const uint4*)xh, (const uint4*)xl, ptr, csr, (uint4*)z1h, (uint4*)z1l);
    mma_gemm_kernel<false><<<gemmGrid, 256, SMTOT>>>(
        z1h, z1l, KP1, w1a, KP1, b1a, h1h, h1l, nullptr, NN, nullptr);
    mma_gemm_kernel<false><<<gemmGrid, 256, SMTOT>>>(
        h1h, h1l, HID, w1b, HID, b1b, hh, hl, nullptr, NN, nullptr);

    // ---- layer 2 ----
    gather_kernel<HID / 8><<<nodeGrid, 256>>>(
        (const uint4*)hh, (const uint4*)hl, ptr, csr, (uint4*)z2h, (uint4*)z2l);
    init_out_kernel<<<(NN * 2 + 255) / 256, 256>>>(out, b2b);
    mma_gemm_kernel<true><<<gemmGrid, 256, SMTOT>>>(
        z2h, z2l, HID, w2a, HID, b2a, nullptr, nullptr, out, NN, W2b);
}

// round 10
// speedup vs baseline: 1.4763x; 1.1804x over previous
#include <cuda_runtime.h>
#include <cuda_fp16.h>
#include <cstdint>

#define NN 50000
#define NE 800000
#define INC 165
#define HID 256
#define KP1 192              // K=165 padded to multiple of 64

// ---------------- scratch (no runtime allocation allowed) ----------------
__device__ int   g_cnt[NN];
__device__ int   g_ptr[NN + 1];
__device__ int   g_cursor[NN];
__device__ int   g_csr[NE];
__device__ __half g_x [(size_t)NN * KP1];
__device__ __half g_z1[(size_t)NN * KP1];
__device__ __half g_h1[(size_t)NN * HID];
__device__ __half g_h [(size_t)NN * HID];
__device__ __half g_z2[(size_t)NN * HID];
__device__ __half g_w1a_hi[HID * KP1];
__device__ __half g_w1a_lo[HID * KP1];
__device__ __half g_w1b_hi[HID * HID];
__device__ __half g_w1b_lo[HID * HID];
__device__ __half g_w2a_hi[HID * HID];
__device__ __half g_w2a_lo[HID * HID];

// ---------------- PTX helpers ----------------
__device__ __forceinline__ uint32_t smem_u32(const void* p) {
    uint32_t a;
    asm("{ .reg .u64 t; cvta.to.shared.u64 t, %1; cvt.u32.u64 %0, t; }" : "=r"(a) : "l"(p));
    return a;
}
__device__ __forceinline__ void ldm_x4(uint32_t* r, uint32_t addr) {
    asm volatile("ldmatrix.sync.aligned.m8n8.x4.shared.b16 {%0,%1,%2,%3}, [%4];"
        : "=r"(r[0]), "=r"(r[1]), "=r"(r[2]), "=r"(r[3]) : "r"(addr));
}
__device__ __forceinline__ void ldm_x2(uint32_t* r, uint32_t addr) {
    asm volatile("ldmatrix.sync.aligned.m8n8.x2.shared.b16 {%0,%1}, [%2];"
        : "=r"(r[0]), "=r"(r[1]) : "r"(addr));
}
__device__ __forceinline__ void mma_f16(float* c, const uint32_t* a, const uint32_t* b) {
    asm volatile("mma.sync.aligned.m16n8k16.row.col.f32.f16.f16.f32 "
        "{%0,%1,%2,%3}, {%4,%5,%6,%7}, {%8,%9}, {%0,%1,%2,%3};"
        : "+f"(c[0]), "+f"(c[1]), "+f"(c[2]), "+f"(c[3])
        : "r"(a[0]), "r"(a[1]), "r"(a[2]), "r"(a[3]), "r"(b[0]), "r"(b[1]));
}
__device__ __forceinline__ void cp16(uint32_t dst, const void* src) {
    asm volatile("cp.async.ca.shared.global [%0], [%1], 16;" :: "r"(dst), "l"(src));
}
__device__ __forceinline__ uint32_t pack2h(float v0, float v1) {
    __half2 h = __floats2half2_rn(v0, v1);   // x = v0 (low), y = v1 (high)
    return *(uint32_t*)&h;
}
__device__ __forceinline__ void acc8(float* a, uint4 h) {
    const uint32_t hu[4] = {h.x, h.y, h.z, h.w};
#pragma unroll
    for (int q = 0; q < 4; q++) {
        float2 fh = __half22float2(*(const __half2*)&hu[q]);
        a[2 * q]     += fh.x;
        a[2 * q + 1] += fh.y;
    }
}

// ---------------------------------------------------------------------------
// CSR build
// ---------------------------------------------------------------------------
__global__ void hist_kernel(const int* __restrict__ dst, int* __restrict__ cnt) {
    int e = blockIdx.x * blockDim.x + threadIdx.x;
    if (e < NE) atomicAdd(&cnt[__ldg(dst + e)], 1);
}

__global__ void scan_kernel(const int* __restrict__ cnt,
                            int* __restrict__ ptr, int* __restrict__ cursor) {
    __shared__ int wsum[32];
    __shared__ int running;
    const int t = threadIdx.x;
    if (t == 0) running = 0;
    __syncthreads();
    for (int base = 0; base < NN; base += 1024) {
        int v = (base + t < NN) ? cnt[base + t] : 0;
        int x = v;
#pragma unroll
        for (int o = 1; o < 32; o <<= 1) {
            int y = __shfl_up_sync(0xffffffffu, x, o);
            if ((t & 31) >= o) x += y;
        }
        if ((t & 31) == 31) wsum[t >> 5] = x;
        __syncthreads();
        if (t < 32) {
            int w = wsum[t];
#pragma unroll
            for (int o = 1; o < 32; o <<= 1) {
                int y = __shfl_up_sync(0xffffffffu, w, o);
                if (t >= o) w += y;
            }
            wsum[t] = w;
        }
        __syncthreads();
        int excl = x - v + ((t >= 32) ? wsum[(t >> 5) - 1] : 0) + running;
        if (base + t < NN) { ptr[base + t] = excl; cursor[base + t] = excl; }
        __syncthreads();
        if (t == 0) running += wsum[31];
        __syncthreads();
    }
    if (t == 0) ptr[NN] = running;
}

__global__ void fill_kernel(const int* __restrict__ src, const int* __restrict__ dst,
                            int* __restrict__ cursor, int* __restrict__ csr) {
    int e = blockIdx.x * blockDim.x + threadIdx.x;
    if (e < NE) {
        int p = atomicAdd(&cursor[__ldg(dst + e)], 1);
        csr[p] = __ldg(src + e);
    }
}

// x [NN][165] fp32 -> fp16 [NN][192], zero-padded
__global__ void pad_kernel(const float* __restrict__ x, __half* __restrict__ xo) {
    int i = blockIdx.x * blockDim.x + threadIdx.x;
    if (i >= NN * (KP1 / 4)) return;
    int n = i / (KP1 / 4), c = (i % (KP1 / 4)) * 4;
    float v[4];
#pragma unroll
    for (int q = 0; q < 4; q++) {
        int cc = c + q;
        v[q] = (cc < INC) ? __ldg(&x[(size_t)n * INC + cc]) : 0.f;
    }
    *(uint32_t*)(xo + (size_t)n * KP1 + c)     = pack2h(v[0], v[1]);
    *(uint32_t*)(xo + (size_t)n * KP1 + c + 2) = pack2h(v[2], v[3]);
}

// ---------------------------------------------------------------------------
// Gather-aggregate (single fp16 plane): z[n] = f[n] + sum_nbr f[nbr].
// Warp per node; lane covers one uint4 (8 fp16 columns). fp32 accum.
// ---------------------------------------------------------------------------
template<int RU4>   // uint4s per row (24 for K=192, 32 for K=256)
__global__ void gather_kernel(const uint4* __restrict__ f,
                              const int* __restrict__ ptr, const int* __restrict__ csr,
                              uint4* __restrict__ z) {
    int n = blockIdx.x * (blockDim.x >> 5) + (threadIdx.x >> 5);
    if (n >= NN) return;
    const int lane = threadIdx.x & 31;
    if (lane >= RU4) return;
    float a[8] = {0, 0, 0, 0, 0, 0, 0, 0};
    acc8(a, __ldg(f + (size_t)n * RU4 + lane));
    const int e0 = __ldg(ptr + n), e1 = __ldg(ptr + n + 1);
    int j = e0;
    for (; j + 3 < e1; j += 4) {
        const size_t b0 = (size_t)__ldg(csr + j)     * RU4;
        const size_t b1 = (size_t)__ldg(csr + j + 1) * RU4;
        const size_t b2 = (size_t)__ldg(csr + j + 2) * RU4;
        const size_t b3 = (size_t)__ldg(csr + j + 3) * RU4;
        uint4 v0 = __ldg(f + b0 + lane), v1 = __ldg(f + b1 + lane);
        uint4 v2 = __ldg(f + b2 + lane), v3 = __ldg(f + b3 + lane);
        acc8(a, v0); acc8(a, v1); acc8(a, v2); acc8(a, v3);
    }
    for (; j < e1; j++) {
        const size_t b0 = (size_t)__ldg(csr + j) * RU4;
        acc8(a, __ldg(f + b0 + lane));
    }
    uint4 o;
    o.x = pack2h(a[0], a[1]);
    o.y = pack2h(a[2], a[3]);
    o.z = pack2h(a[4], a[5]);
    o.w = pack2h(a[6], a[7]);
    z[(size_t)n * RU4 + lane] = o;
}

// ---------------------------------------------------------------------------
// Weight prep: W[K,N] fp32 -> W^T fp16 hi/lo planes, [N][Kp], zero-padded.
// ---------------------------------------------------------------------------
__global__ void prep_w_kernel(const float* __restrict__ W,
                              __half* __restrict__ hi, __half* __restrict__ lo,
                              int K, int N, int Kp) {
    int i = blockIdx.x * blockDim.x + threadIdx.x;
    if (i >= N * Kp) return;
    int n = i / Kp, k = i % Kp;
    float w = (k < K) ? __ldg(&W[(size_t)k * N + n]) : 0.f;
    __half h = __float2half_rn(w);
    hi[i] = h;
    lo[i] = __float2half_rn(w - __half2float(h));
}

__global__ void init_out_kernel(float* __restrict__ out, const float* __restrict__ b2) {
    int i = blockIdx.x * blockDim.x + threadIdx.x;
    if (i < NN * 2) out[i] = __ldg(b2 + (i & 1));
}

// ---------------------------------------------------------------------------
// Single-stage cp.async warp-MMA GEMM: C = A @ (Bhi + Blo), fp16, fp32 accum.
// A single fp16 plane; W split hi/lo (exact to ~2^-22). 2 MMAs per pair.
// CTA tile 128x128, 8 warps 4Mx2N, warp tile 32x64, >=2 CTA/SM.
// Non-OUTP epilogue: relu(acc+bias) -> single fp16 plane.
// OUTP: relu(acc+bias) projected on w2[256][2], atomicAdd into Cout[M][2].
// ---------------------------------------------------------------------------
#define SROW 72
#define SMAT (128 * SROW * 2)      // 18432 B per tile
#define OFF_A   0
#define OFF_BHI (SMAT)
#define OFF_BLO (2 * SMAT)
#define SMTOT (3 * SMAT)           // 55296 B

template<bool OUTP>
__global__ __launch_bounds__(256, 2)
void mma_gemm_kernel(const __half* __restrict__ A, int lda,
                     const __half* __restrict__ Bh,
                     const __half* __restrict__ Bl, int Kp,
                     const float* __restrict__ bias,
                     __half* __restrict__ C,
                     float* __restrict__ Cout, int M,
                     const float* __restrict__ w2) {
    extern __shared__ __align__(16) char smem[];
    const uint32_t sb = smem_u32(smem);
    const int tid = threadIdx.x, wid = tid >> 5, lane = tid & 31;

    const int bm0 = blockIdx.y * 128;
    const int n0 = blockIdx.x * 128;

    const int arow = tid >> 1;
    const int acol0 = (tid & 1) * 32;
    const int mw = (wid >> 1) * 32;
    const int nw = (wid & 1) * 64;

    const int gRow = bm0 + arow;
    const __half* pA  = A  + (size_t)(gRow < M ? gRow : 0) * lda + acol0;
    const __half* pBh = Bh + (size_t)(n0 + arow) * Kp + acol0;
    const __half* pBl = Bl + (size_t)(n0 + arow) * Kp + acol0;
    const uint32_t sdst = sb + (uint32_t)(arow * SROW + acol0) * 2;

    const int nchunks = Kp >> 6;

    float acc[2][8][4];
#pragma unroll
    for (int ms = 0; ms < 2; ms++)
#pragma unroll
        for (int ns = 0; ns < 8; ns++)
#pragma unroll
            for (int q = 0; q < 4; q++) acc[ms][ns][q] = 0.f;

    const int l7 = lane & 7;
    const int aRowAdd = ((lane >> 3) & 1) * 8;
    const int aKAdd = (lane >> 4) * 8;
    const int bl = lane & 15;
    const int bRow = bl & 7;
    const int bKAdd = ((bl >> 3) & 1) * 8;

    for (int ch = 0; ch < nchunks; ch++) {
        const int k0 = ch << 6;
#pragma unroll
        for (int q = 0; q < 4; q++) {
            cp16(sdst + OFF_A   + q * 16, pA  + k0 + q * 8);
            cp16(sdst + OFF_BHI + q * 16, pBh + k0 + q * 8);
            cp16(sdst + OFF_BLO + q * 16, pBl + k0 + q * 8);
        }
        asm volatile("cp.async.commit_group;" ::: "memory");
        asm volatile("cp.async.wait_group 0;" ::: "memory");
        __syncthreads();

#pragma unroll
        for (int kk = 0; kk < 64; kk += 16) {
            uint32_t av[2][4], bhi[8][2], blo[8][2];
#pragma unroll
            for (int ms = 0; ms < 2; ms++) {
                uint32_t ra = sb + (uint32_t)((mw + ms * 16 + l7 + aRowAdd) * SROW + kk + aKAdd) * 2;
                ldm_x4(av[ms], ra + OFF_A);
            }
#pragma unroll
            for (int ns = 0; ns < 8; ns++) {
                uint32_t rb = sb + (uint32_t)((nw + ns * 8 + bRow) * SROW + kk + bKAdd) * 2;
                ldm_x2(bhi[ns], rb + OFF_BHI);
                ldm_x2(blo[ns], rb + OFF_BLO);
            }
#pragma unroll
            for (int ms = 0; ms < 2; ms++)
#pragma unroll
                for (int ns = 0; ns < 8; ns++) {
                    mma_f16(acc[ms][ns], av[ms], bhi[ns]);
                    mma_f16(acc[ms][ns], av[ms], blo[ns]);
                }
        }
        __syncthreads();
    }

    const int r = lane >> 2;
    const int cp = (lane & 3) * 2;

    if (OUTP) {
        float s[2][2][2];
#pragma unroll
        for (int ms = 0; ms < 2; ms++)
#pragma unroll
            for (int rh = 0; rh < 2; rh++) { s[ms][rh][0] = 0.f; s[ms][rh][1] = 0.f; }
#pragma unroll
        for (int ms = 0; ms < 2; ms++)
#pragma unroll
            for (int ns = 0; ns < 8; ns++) {
                const int col = n0 + nw + ns * 8 + cp;
                const float2 bb = *(const float2*)(bias + col);
                const float2 w0 = *(const float2*)(w2 + col * 2);
                const float2 w1 = *(const float2*)(w2 + (col + 1) * 2);
                float v0 = fmaxf(acc[ms][ns][0] + bb.x, 0.f);
                float v1 = fmaxf(acc[ms][ns][1] + bb.y, 0.f);
                float v2 = fmaxf(acc[ms][ns][2] + bb.x, 0.f);
                float v3 = fmaxf(acc[ms][ns][3] + bb.y, 0.f);
                s[ms][0][0] += v0 * w0.x + v1 * w1.x;
                s[ms][0][1] += v0 * w0.y + v1 * w1.y;
                s[ms][1][0] += v2 * w0.x + v3 * w1.x;
                s[ms][1][1] += v2 * w0.y + v3 * w1.y;
            }
#pragma unroll
        for (int ms = 0; ms < 2; ms++)
#pragma unroll
            for (int rh = 0; rh < 2; rh++)
#pragma unroll
                for (int oc = 0; oc < 2; oc++) {
                    float v = s[ms][rh][oc];
                    v += __shfl_xor_sync(0xffffffffu, v, 1);
                    v += __shfl_xor_sync(0xffffffffu, v, 2);
                    s[ms][rh][oc] = v;
                }
        if ((lane & 3) == 0) {
#pragma unroll
            for (int ms = 0; ms < 2; ms++)
#pragma unroll
                for (int rh = 0; rh < 2; rh++) {
                    const int row = bm0 + mw + ms * 16 + r + rh * 8;
                    if (row < M) {
                        atomicAdd(Cout + (size_t)row * 2 + 0, s[ms][rh][0]);
                        atomicAdd(Cout + (size_t)row * 2 + 1, s[ms][rh][1]);
                    }
                }
        }
    } else {
#pragma unroll
        for (int ms = 0; ms < 2; ms++)
#pragma unroll
            for (int ns = 0; ns < 8; ns++) {
                const int col = n0 + nw + ns * 8 + cp;
                const float2 bb = *(const float2*)(bias + col);
                const int row0 = bm0 + mw + ms * 16 + r;
                float v0 = fmaxf(acc[ms][ns][0] + bb.x, 0.f);
                float v1 = fmaxf(acc[ms][ns][1] + bb.y, 0.f);
                float v2 = fmaxf(acc[ms][ns][2] + bb.x, 0.f);
                float v3 = fmaxf(acc[ms][ns][3] + bb.y, 0.f);
#pragma unroll
                for (int rh = 0; rh < 2; rh++) {
                    const int row = row0 + rh * 8;
                    if (row >= M) continue;
                    *(uint32_t*)(C + (size_t)row * HID + col) =
                        pack2h(rh ? v2 : v0, rh ? v3 : v1);
                }
            }
    }
}

// ---------------------------------------------------------------------------
extern "C" void kernel_launch(void* const* d_in, const int* in_sizes, int n_in,
                              void* d_out, int out_size) {
    const float* x   = (const float*)d_in[0];
    const int*   ei  = (const int*)d_in[1];
    const float* W1a = (const float*)d_in[2];
    const float* b1a = (const float*)d_in[3];
    const float* W1b = (const float*)d_in[4];
    const float* b1b = (const float*)d_in[5];
    const float* W2a = (const float*)d_in[6];
    const float* b2a = (const float*)d_in[7];
    const float* W2b = (const float*)d_in[8];
    const float* b2b = (const float*)d_in[9];
    float* out = (float*)d_out;

    const int* src = ei;
    const int* dst = ei + NE;

    int *cnt, *ptr, *cursor, *csr;
    __half *xp, *z1, *h1, *h, *z2;
    __half *w1ah, *w1al, *w1bh, *w1bl, *w2ah, *w2al;
    cudaGetSymbolAddress((void**)&cnt,    g_cnt);
    cudaGetSymbolAddress((void**)&ptr,    g_ptr);
    cudaGetSymbolAddress((void**)&cursor, g_cursor);
    cudaGetSymbolAddress((void**)&csr,    g_csr);
    cudaGetSymbolAddress((void**)&xp,     g_x);
    cudaGetSymbolAddress((void**)&z1,     g_z1);
    cudaGetSymbolAddress((void**)&h1,     g_h1);
    cudaGetSymbolAddress((void**)&h,      g_h);
    cudaGetSymbolAddress((void**)&z2,     g_z2);
    cudaGetSymbolAddress((void**)&w1ah,   g_w1a_hi);
    cudaGetSymbolAddress((void**)&w1al,   g_w1a_lo);
    cudaGetSymbolAddress((void**)&w1bh,   g_w1b_hi);
    cudaGetSymbolAddress((void**)&w1bl,   g_w1b_lo);
    cudaGetSymbolAddress((void**)&w2ah,   g_w2a_hi);
    cudaGetSymbolAddress((void**)&w2al,   g_w2a_lo);

    cudaFuncSetAttribute(mma_gemm_kernel<false>,
                         cudaFuncAttributeMaxDynamicSharedMemorySize, SMTOT);
    cudaFuncSetAttribute(mma_gemm_kernel<true>,
                         cudaFuncAttributeMaxDynamicSharedMemorySize, SMTOT);

    const dim3 gemmGrid(2, (NN + 127) / 128);
    const int edgeGrid = (NE + 255) / 256;
    const int nodeGrid = (NN + 7) / 8;

    // ---- CSR build + pad x ----
    cudaMemsetAsync(cnt, 0, sizeof(int) * NN);
    hist_kernel<<<edgeGrid, 256>>>(dst, cnt);
    pad_kernel<<<(NN * (KP1 / 4) + 255) / 256, 256>>>(x, xp);
    scan_kernel<<<1, 1024>>>(cnt, ptr, cursor);
    fill_kernel<<<edgeGrid, 256>>>(src, dst, cursor, csr);

    // ---- weight prep (fp16 hi/lo planes) ----
    prep_w_kernel<<<(HID * KP1 + 255) / 256, 256>>>(W1a, w1ah, w1al, INC, HID, KP1);
    prep_w_kernel<<<(HID * HID + 255) / 256, 256>>>(W1b, w1bh, w1bl, HID, HID, HID);
    prep_w_kernel<<<(HID * HID + 255) / 256, 256>>>(W2a, w2ah, w2al, HID, HID, HID);

    // ---- layer 1 ----
    gather_kernel<KP1 / 8><<<nodeGrid, 256>>>((const uint4*)xp, ptr, csr, (uint4*)z1);
    mma_gemm_kernel<false><<<gemmGrid, 256, SMTOT>>>(
        z1, KP1, w1ah, w1al, KP1, b1a, h1, nullptr, NN, nullptr);
    mma_gemm_kernel<false><<<gemmGrid, 256, SMTOT>>>(
        h1, HID, w1bh, w1bl, HID, b1b, h, nullptr, NN, nullptr);

    // ---- layer 2 ----
    gather_kernel<HID / 8><<<nodeGrid, 256>>>((const uint4*)h, ptr, csr, (uint4*)z2);
    init_out_kernel<<<(NN * 2 + 255) / 256, 256>>>(out, b2b);
    mma_gemm_kernel<true><<<gemmGrid, 256, SMTOT>>>(
        z2, HID, w2ah, w2al, HID, b2a, nullptr, out, NN, W2b);
}

// round 11
// speedup vs baseline: 1.8217x; 1.2340x over previous
#include <cuda_runtime.h>
#include <cuda_fp16.h>
#include <cstdint>

#define NN 50000
#define NE 800000
#define INC 165
#define HID 256
#define KP1 192              // K=165 padded to multiple of 64

// ---------------- scratch (no runtime allocation allowed) ----------------
__device__ int   g_cnt[NN];
__device__ int   g_ptr[NN + 1];
__device__ int   g_cursor[NN];
__device__ int   g_csr[NE];
__device__ __half g_x [(size_t)NN * KP1];
__device__ __half g_z1[(size_t)NN * KP1];
__device__ __half g_h1[(size_t)NN * HID];
__device__ __half g_h [(size_t)NN * HID];
__device__ __half g_z2[(size_t)NN * HID];
__device__ __half g_w1a[HID * KP1];
__device__ __half g_w1b[HID * HID];
__device__ __half g_w2a[HID * HID];

// ---------------- PTX helpers ----------------
__device__ __forceinline__ uint32_t smem_u32(const void* p) {
    uint32_t a;
    asm("{ .reg .u64 t; cvta.to.shared.u64 t, %1; cvt.u32.u64 %0, t; }" : "=r"(a) : "l"(p));
    return a;
}
__device__ __forceinline__ void ldm_x4(uint32_t* r, uint32_t addr) {
    asm volatile("ldmatrix.sync.aligned.m8n8.x4.shared.b16 {%0,%1,%2,%3}, [%4];"
        : "=r"(r[0]), "=r"(r[1]), "=r"(r[2]), "=r"(r[3]) : "r"(addr));
}
__device__ __forceinline__ void ldm_x2(uint32_t* r, uint32_t addr) {
    asm volatile("ldmatrix.sync.aligned.m8n8.x2.shared.b16 {%0,%1}, [%2];"
        : "=r"(r[0]), "=r"(r[1]) : "r"(addr));
}
__device__ __forceinline__ void mma_f16(float* c, const uint32_t* a, const uint32_t* b) {
    asm volatile("mma.sync.aligned.m16n8k16.row.col.f32.f16.f16.f32 "
        "{%0,%1,%2,%3}, {%4,%5,%6,%7}, {%8,%9}, {%0,%1,%2,%3};"
        : "+f"(c[0]), "+f"(c[1]), "+f"(c[2]), "+f"(c[3])
        : "r"(a[0]), "r"(a[1]), "r"(a[2]), "r"(a[3]), "r"(b[0]), "r"(b[1]));
}
__device__ __forceinline__ void cp16(uint32_t dst, const void* src) {
    asm volatile("cp.async.ca.shared.global [%0], [%1], 16;" :: "r"(dst), "l"(src));
}
__device__ __forceinline__ uint32_t pack2h(float v0, float v1) {
    __half2 h = __floats2half2_rn(v0, v1);   // x = v0 (low), y = v1 (high)
    return *(uint32_t*)&h;
}
__device__ __forceinline__ void acc8(float* a, uint4 h) {
    const uint32_t hu[4] = {h.x, h.y, h.z, h.w};
#pragma unroll
    for (int q = 0; q < 4; q++) {
        float2 fh = __half22float2(*(const __half2*)&hu[q]);
        a[2 * q]     += fh.x;
        a[2 * q + 1] += fh.y;
    }
}

// ---------------------------------------------------------------------------
// CSR build
// ---------------------------------------------------------------------------
__global__ void hist_kernel(const int* __restrict__ dst, int* __restrict__ cnt) {
    int e = blockIdx.x * blockDim.x + threadIdx.x;
    if (e < NE) atomicAdd(&cnt[__ldg(dst + e)], 1);
}

__global__ void scan_kernel(const int* __restrict__ cnt,
                            int* __restrict__ ptr, int* __restrict__ cursor) {
    __shared__ int wsum[32];
    __shared__ int running;
    const int t = threadIdx.x;
    if (t == 0) running = 0;
    __syncthreads();
    for (int base = 0; base < NN; base += 1024) {
        int v = (base + t < NN) ? cnt[base + t] : 0;
        int x = v;
#pragma unroll
        for (int o = 1; o < 32; o <<= 1) {
            int y = __shfl_up_sync(0xffffffffu, x, o);
            if ((t & 31) >= o) x += y;
        }
        if ((t & 31) == 31) wsum[t >> 5] = x;
        __syncthreads();
        if (t < 32) {
            int w = wsum[t];
#pragma unroll
            for (int o = 1; o < 32; o <<= 1) {
                int y = __shfl_up_sync(0xffffffffu, w, o);
                if (t >= o) w += y;
            }
            wsum[t] = w;
        }
        __syncthreads();
        int excl = x - v + ((t >= 32) ? wsum[(t >> 5) - 1] : 0) + running;
        if (base + t < NN) { ptr[base + t] = excl; cursor[base + t] = excl; }
        __syncthreads();
        if (t == 0) running += wsum[31];
        __syncthreads();
    }
    if (t == 0) ptr[NN] = running;
}

__global__ void fill_kernel(const int* __restrict__ src, const int* __restrict__ dst,
                            int* __restrict__ cursor, int* __restrict__ csr) {
    int e = blockIdx.x * blockDim.x + threadIdx.x;
    if (e < NE) {
        int p = atomicAdd(&cursor[__ldg(dst + e)], 1);
        csr[p] = __ldg(src + e);
    }
}

// x [NN][165] fp32 -> fp16 [NN][192], zero-padded
__global__ void pad_kernel(const float* __restrict__ x, __half* __restrict__ xo) {
    int i = blockIdx.x * blockDim.x + threadIdx.x;
    if (i >= NN * (KP1 / 4)) return;
    int n = i / (KP1 / 4), c = (i % (KP1 / 4)) * 4;
    float v[4];
#pragma unroll
    for (int q = 0; q < 4; q++) {
        int cc = c + q;
        v[q] = (cc < INC) ? __ldg(&x[(size_t)n * INC + cc]) : 0.f;
    }
    *(uint32_t*)(xo + (size_t)n * KP1 + c)     = pack2h(v[0], v[1]);
    *(uint32_t*)(xo + (size_t)n * KP1 + c + 2) = pack2h(v[2], v[3]);
}

// ---------------------------------------------------------------------------
// Gather-aggregate (single fp16 plane): z[n] = f[n] + sum_nbr f[nbr].
// Warp per node; lane covers one uint4 (8 fp16 columns). fp32 accum.
// ---------------------------------------------------------------------------
template<int RU4>   // uint4s per row (24 for K=192, 32 for K=256)
__global__ void gather_kernel(const uint4* __restrict__ f,
                              const int* __restrict__ ptr, const int* __restrict__ csr,
                              uint4* __restrict__ z) {
    int n = blockIdx.x * (blockDim.x >> 5) + (threadIdx.x >> 5);
    if (n >= NN) return;
    const int lane = threadIdx.x & 31;
    if (lane >= RU4) return;
    float a[8] = {0, 0, 0, 0, 0, 0, 0, 0};
    acc8(a, __ldg(f + (size_t)n * RU4 + lane));
    const int e0 = __ldg(ptr + n), e1 = __ldg(ptr + n + 1);
    int j = e0;
    for (; j + 3 < e1; j += 4) {
        const size_t b0 = (size_t)__ldg(csr + j)     * RU4;
        const size_t b1 = (size_t)__ldg(csr + j + 1) * RU4;
        const size_t b2 = (size_t)__ldg(csr + j + 2) * RU4;
        const size_t b3 = (size_t)__ldg(csr + j + 3) * RU4;
        uint4 v0 = __ldg(f + b0 + lane), v1 = __ldg(f + b1 + lane);
        uint4 v2 = __ldg(f + b2 + lane), v3 = __ldg(f + b3 + lane);
        acc8(a, v0); acc8(a, v1); acc8(a, v2); acc8(a, v3);
    }
    for (; j < e1; j++) {
        const size_t b0 = (size_t)__ldg(csr + j) * RU4;
        acc8(a, __ldg(f + b0 + lane));
    }
    uint4 o;
    o.x = pack2h(a[0], a[1]);
    o.y = pack2h(a[2], a[3]);
    o.z = pack2h(a[4], a[5]);
    o.w = pack2h(a[6], a[7]);
    z[(size_t)n * RU4 + lane] = o;
}

// ---------------------------------------------------------------------------
// Weight prep: W[K,N] fp32 -> W^T fp16 (single plane), [N][Kp], zero-padded.
// ---------------------------------------------------------------------------
__global__ void prep_w_kernel(const float* __restrict__ W,
                              __half* __restrict__ hi,
                              int K, int N, int Kp) {
    int i = blockIdx.x * blockDim.x + threadIdx.x;
    if (i >= N * Kp) return;
    int n = i / Kp, k = i % Kp;
    float w = (k < K) ? __ldg(&W[(size_t)k * N + n]) : 0.f;
    hi[i] = __float2half_rn(w);
}

__global__ void init_out_kernel(float* __restrict__ out, const float* __restrict__ b2) {
    int i = blockIdx.x * blockDim.x + threadIdx.x;
    if (i < NN * 2) out[i] = __ldg(b2 + (i & 1));
}

// ---------------------------------------------------------------------------
// Single-stage cp.async warp-MMA GEMM: C = A @ B, fp16 x fp16, fp32 accum.
// 1 MMA per fragment pair. CTA tile 128x128, 8 warps 4Mx2N, warp tile 32x64.
// Non-OUTP epilogue: relu(acc+bias) -> single fp16 plane.
// OUTP: relu(acc+bias) projected on w2[256][2], atomicAdd into Cout[M][2].
// ---------------------------------------------------------------------------
#define SROW 72
#define SMAT (128 * SROW * 2)      // 18432 B per tile
#define OFF_A 0
#define OFF_B (SMAT)
#define SMTOT (2 * SMAT)           // 36864 B

template<bool OUTP>
__global__ __launch_bounds__(256, 2)
void mma_gemm_kernel(const __half* __restrict__ A, int lda,
                     const __half* __restrict__ B, int Kp,
                     const float* __restrict__ bias,
                     __half* __restrict__ C,
                     float* __restrict__ Cout, int M,
                     const float* __restrict__ w2) {
    extern __shared__ __align__(16) char smem[];
    const uint32_t sb = smem_u32(smem);
    const int tid = threadIdx.x, wid = tid >> 5, lane = tid & 31;

    const int bm0 = blockIdx.y * 128;
    const int n0 = blockIdx.x * 128;

    const int arow = tid >> 1;
    const int acol0 = (tid & 1) * 32;
    const int mw = (wid >> 1) * 32;
    const int nw = (wid & 1) * 64;

    const int gRow = bm0 + arow;
    const __half* pA = A + (size_t)(gRow < M ? gRow : 0) * lda + acol0;
    const __half* pB = B + (size_t)(n0 + arow) * Kp + acol0;
    const uint32_t sdst = sb + (uint32_t)(arow * SROW + acol0) * 2;

    const int nchunks = Kp >> 6;

    float acc[2][8][4];
#pragma unroll
    for (int ms = 0; ms < 2; ms++)
#pragma unroll
        for (int ns = 0; ns < 8; ns++)
#pragma unroll
            for (int q = 0; q < 4; q++) acc[ms][ns][q] = 0.f;

    const int l7 = lane & 7;
    const int aRowAdd = ((lane >> 3) & 1) * 8;
    const int aKAdd = (lane >> 4) * 8;
    const int bl = lane & 15;
    const int bRow = bl & 7;
    const int bKAdd = ((bl >> 3) & 1) * 8;

    for (int ch = 0; ch < nchunks; ch++) {
        const int k0 = ch << 6;
#pragma unroll
        for (int q = 0; q < 4; q++) {
            cp16(sdst + OFF_A + q * 16, pA + k0 + q * 8);
            cp16(sdst + OFF_B + q * 16, pB + k0 + q * 8);
        }
        asm volatile("cp.async.commit_group;" ::: "memory");
        asm volatile("cp.async.wait_group 0;" ::: "memory");
        __syncthreads();

#pragma unroll
        for (int kk = 0; kk < 64; kk += 16) {
            uint32_t av[2][4], bv[8][2];
#pragma unroll
            for (int ms = 0; ms < 2; ms++) {
                uint32_t ra = sb + (uint32_t)((mw + ms * 16 + l7 + aRowAdd) * SROW + kk + aKAdd) * 2;
                ldm_x4(av[ms], ra + OFF_A);
            }
#pragma unroll
            for (int ns = 0; ns < 8; ns++) {
                uint32_t rb = sb + (uint32_t)((nw + ns * 8 + bRow) * SROW + kk + bKAdd) * 2;
                ldm_x2(bv[ns], rb + OFF_B);
            }
#pragma unroll
            for (int ms = 0; ms < 2; ms++)
#pragma unroll
                for (int ns = 0; ns < 8; ns++)
                    mma_f16(acc[ms][ns], av[ms], bv[ns]);
        }
        __syncthreads();
    }

    const int r = lane >> 2;
    const int cp = (lane & 3) * 2;

    if (OUTP) {
        float s[2][2][2];
#pragma unroll
        for (int ms = 0; ms < 2; ms++)
#pragma unroll
            for (int rh = 0; rh < 2; rh++) { s[ms][rh][0] = 0.f; s[ms][rh][1] = 0.f; }
#pragma unroll
        for (int ms = 0; ms < 2; ms++)
#pragma unroll
            for (int ns = 0; ns < 8; ns++) {
                const int col = n0 + nw + ns * 8 + cp;
                const float2 bb = *(const float2*)(bias + col);
                const float2 w0 = *(const float2*)(w2 + col * 2);
                const float2 w1 = *(const float2*)(w2 + (col + 1) * 2);
                float v0 = fmaxf(acc[ms][ns][0] + bb.x, 0.f);
                float v1 = fmaxf(acc[ms][ns][1] + bb.y, 0.f);
                float v2 = fmaxf(acc[ms][ns][2] + bb.x, 0.f);
                float v3 = fmaxf(acc[ms][ns][3] + bb.y, 0.f);
                s[ms][0][0] += v0 * w0.x + v1 * w1.x;
                s[ms][0][1] += v0 * w0.y + v1 * w1.y;
                s[ms][1][0] += v2 * w0.x + v3 * w1.x;
                s[ms][1][1] += v2 * w0.y + v3 * w1.y;
            }
#pragma unroll
        for (int ms = 0; ms < 2; ms++)
#pragma unroll
            for (int rh = 0; rh < 2; rh++)
#pragma unroll
                for (int oc = 0; oc < 2; oc++) {
                    float v = s[ms][rh][oc];
                    v += __shfl_xor_sync(0xffffffffu, v, 1);
                    v += __shfl_xor_sync(0xffffffffu, v, 2);
                    s[ms][rh][oc] = v;
                }
        if ((lane & 3) == 0) {
#pragma unroll
            for (int ms = 0; ms < 2; ms++)
#pragma unroll
                for (int rh = 0; rh < 2; rh++) {
                    const int row = bm0 + mw + ms * 16 + r + rh * 8;
                    if (row < M) {
                        atomicAdd(Cout + (size_t)row * 2 + 0, s[ms][rh][0]);
                        atomicAdd(Cout + (size_t)row * 2 + 1, s[ms][rh][1]);
                    }
                }
        }
    } else {
#pragma unroll
        for (int ms = 0; ms < 2; ms++)
#pragma unroll
            for (int ns = 0; ns < 8; ns++) {
                const int col = n0 + nw + ns * 8 + cp;
                const float2 bb = *(const float2*)(bias + col);
                const int row0 = bm0 + mw + ms * 16 + r;
                float v0 = fmaxf(acc[ms][ns][0] + bb.x, 0.f);
                float v1 = fmaxf(acc[ms][ns][1] + bb.y, 0.f);
                float v2 = fmaxf(acc[ms][ns][2] + bb.x, 0.f);
                float v3 = fmaxf(acc[ms][ns][3] + bb.y, 0.f);
#pragma unroll
                for (int rh = 0; rh < 2; rh++) {
                    const int row = row0 + rh * 8;
                    if (row >= M) continue;
                    *(uint32_t*)(C + (size_t)row * HID + col) =
                        pack2h(rh ? v2 : v0, rh ? v3 : v1);
                }
            }
    }
}

// ---------------------------------------------------------------------------
extern "C" void kernel_launch(void* const* d_in, const int* in_sizes, int n_in,
                              void* d_out, int out_size) {
    const float* x   = (const float*)d_in[0];
    const int*   ei  = (const int*)d_in[1];
    const float* W1a = (const float*)d_in[2];
    const float* b1a = (const float*)d_in[3];
    const float* W1b = (const float*)d_in[4];
    const float* b1b = (const float*)d_in[5];
    const float* W2a = (const float*)d_in[6];
    const float* b2a = (const float*)d_in[7];
    const float* W2b = (const float*)d_in[8];
    const float* b2b = (const float*)d_in[9];
    float* out = (float*)d_out;

    const int* src = ei;
    const int* dst = ei + NE;

    int *cnt, *ptr, *cursor, *csr;
    __half *xp, *z1, *h1, *h, *z2;
    __half *w1a, *w1b, *w2a;
    cudaGetSymbolAddress((void**)&cnt,    g_cnt);
    cudaGetSymbolAddress((void**)&ptr,    g_ptr);
    cudaGetSymbolAddress((void**)&cursor, g_cursor);
    cudaGetSymbolAddress((void**)&csr,    g_csr);
    cudaGetSymbolAddress((void**)&xp,     g_x);
    cudaGetSymbolAddress((void**)&z1,     g_z1);
    cudaGetSymbolAddress((void**)&h1,     g_h1);
    cudaGetSymbolAddress((void**)&h,      g_h);
    cudaGetSymbolAddress((void**)&z2,     g_z2);
    cudaGetSymbolAddress((void**)&w1a,    g_w1a);
    cudaGetSymbolAddress((void**)&w1b,    g_w1b);
    cudaGetSymbolAddress((void**)&w2a,    g_w2a);

    cudaFuncSetAttribute(mma_gemm_kernel<false>,
                         cudaFuncAttributeMaxDynamicSharedMemorySize, SMTOT);
    cudaFuncSetAttribute(mma_gemm_kernel<true>,
                         cudaFuncAttributeMaxDynamicSharedMemorySize, SMTOT);

    const dim3 gemmGrid(2, (NN + 127) / 128);
    const int edgeGrid = (NE + 255) / 256;
    const int nodeGrid = (NN + 7) / 8;

    // ---- CSR build + pad x ----
    cudaMemsetAsync(cnt, 0, sizeof(int) * NN);
    hist_kernel<<<edgeGrid, 256>>>(dst, cnt);
    pad_kernel<<<(NN * (KP1 / 4) + 255) / 256, 256>>>(x, xp);
    scan_kernel<<<1, 1024>>>(cnt, ptr, cursor);
    fill_kernel<<<edgeGrid, 256>>>(src, dst, cursor, csr);

    // ---- weight prep (single fp16 plane) ----
    prep_w_kernel<<<(HID * KP1 + 255) / 256, 256>>>(W1a, w1a, INC, HID, KP1);
    prep_w_kernel<<<(HID * HID + 255) / 256, 256>>>(W1b, w1b, HID, HID, HID);
    prep_w_kernel<<<(HID * HID + 255) / 256, 256>>>(W2a, w2a, HID, HID, HID);

    // ---- layer 1 ----
    gather_kernel<KP1 / 8><<<nodeGrid, 256>>>((const uint4*)xp, ptr, csr, (uint4*)z1);
    mma_gemm_kernel<false><<<gemmGrid, 256, SMTOT>>>(
        z1, KP1, w1a, KP1, b1a, h1, nullptr, NN, nullptr);
    mma_gemm_kernel<false><<<gemmGrid, 256, SMTOT>>>(
        h1, HID, w1b, HID, b1b, h, nullptr, NN, nullptr);

    // ---- layer 2 ----
    gather_kernel<HID / 8><<<nodeGrid, 256>>>((const uint4*)h, ptr, csr, (uint4*)z2);
    init_out_kernel<<<(NN * 2 + 255) / 256, 256>>>(out, b2b);
    mma_gemm_kernel<true><<<gemmGrid, 256, SMTOT>>>(
        z2, HID, w2a, HID, b2a, nullptr, out, NN, W2b);
}

// round 12
// speedup vs baseline: 1.8278x; 1.0033x over previous
#include <cuda_runtime.h>
#include <cuda_fp16.h>
#include <cstdint>

#define NN 50000
#define NE 800000
#define INC 165
#define HID 256
#define KP1 192              // K=165 padded to multiple of 64

// ---------------- scratch (no runtime allocation allowed) ----------------
__device__ int   g_cnt[NN];
__device__ int   g_ptr[NN + 1];
__device__ int   g_cursor[NN];
__device__ int   g_csr[NE];
__device__ __half g_x [(size_t)NN * KP1];
__device__ __half g_z1[(size_t)NN * KP1];
__device__ __half g_h1[(size_t)NN * HID];
__device__ __half g_h [(size_t)NN * HID];
__device__ __half g_z2[(size_t)NN * HID];
__device__ __half g_w1a[HID * KP1];
__device__ __half g_w1b[HID * HID];
__device__ __half g_w2a[HID * HID];

// ---------------- PTX helpers ----------------
__device__ __forceinline__ uint32_t smem_u32(const void* p) {
    uint32_t a;
    asm("{ .reg .u64 t; cvta.to.shared.u64 t, %1; cvt.u32.u64 %0, t; }" : "=r"(a) : "l"(p));
    return a;
}
__device__ __forceinline__ void ldm_x4(uint32_t* r, uint32_t addr) {
    asm volatile("ldmatrix.sync.aligned.m8n8.x4.shared.b16 {%0,%1,%2,%3}, [%4];"
        : "=r"(r[0]), "=r"(r[1]), "=r"(r[2]), "=r"(r[3]) : "r"(addr));
}
__device__ __forceinline__ void ldm_x2(uint32_t* r, uint32_t addr) {
    asm volatile("ldmatrix.sync.aligned.m8n8.x2.shared.b16 {%0,%1}, [%2];"
        : "=r"(r[0]), "=r"(r[1]) : "r"(addr));
}
__device__ __forceinline__ void mma_f16(float* c, const uint32_t* a, const uint32_t* b) {
    asm volatile("mma.sync.aligned.m16n8k16.row.col.f32.f16.f16.f32 "
        "{%0,%1,%2,%3}, {%4,%5,%6,%7}, {%8,%9}, {%0,%1,%2,%3};"
        : "+f"(c[0]), "+f"(c[1]), "+f"(c[2]), "+f"(c[3])
        : "r"(a[0]), "r"(a[1]), "r"(a[2]), "r"(a[3]), "r"(b[0]), "r"(b[1]));
}
__device__ __forceinline__ void cp16(uint32_t dst, const void* src) {
    asm volatile("cp.async.ca.shared.global [%0], [%1], 16;" :: "r"(dst), "l"(src));
}
__device__ __forceinline__ uint32_t pack2h(float v0, float v1) {
    __half2 h = __floats2half2_rn(v0, v1);   // x = v0 (low), y = v1 (high)
    return *(uint32_t*)&h;
}
__device__ __forceinline__ void acc8(float* a, uint4 h) {
    const uint32_t hu[4] = {h.x, h.y, h.z, h.w};
#pragma unroll
    for (int q = 0; q < 4; q++) {
        float2 fh = __half22float2(*(const __half2*)&hu[q]);
        a[2 * q]     += fh.x;
        a[2 * q + 1] += fh.y;
    }
}

// ---------------------------------------------------------------------------
// CSR build (ILP-4 variants: 4 independent edges per thread -> MLP 4)
// ---------------------------------------------------------------------------
__global__ void hist_kernel(const int* __restrict__ dst, int* __restrict__ cnt) {
    int e = (blockIdx.x * blockDim.x + threadIdx.x) * 4;
#pragma unroll
    for (int q = 0; q < 4; q++) {
        int ee = e + q;
        if (ee < NE) atomicAdd(&cnt[__ldg(dst + ee)], 1);
    }
}

__global__ void scan_kernel(const int* __restrict__ cnt,
                            int* __restrict__ ptr, int* __restrict__ cursor) {
    __shared__ int wsum[32];
    __shared__ int running;
    const int t = threadIdx.x;
    if (t == 0) running = 0;
    __syncthreads();
    for (int base = 0; base < NN; base += 1024) {
        int v = (base + t < NN) ? cnt[base + t] : 0;
        int x = v;
#pragma unroll
        for (int o = 1; o < 32; o <<= 1) {
            int y = __shfl_up_sync(0xffffffffu, x, o);
            if ((t & 31) >= o) x += y;
        }
        if ((t & 31) == 31) wsum[t >> 5] = x;
        __syncthreads();
        if (t < 32) {
            int w = wsum[t];
#pragma unroll
            for (int o = 1; o < 32; o <<= 1) {
                int y = __shfl_up_sync(0xffffffffu, w, o);
                if (t >= o) w += y;
            }
            wsum[t] = w;
        }
        __syncthreads();
        int excl = x - v + ((t >= 32) ? wsum[(t >> 5) - 1] : 0) + running;
        if (base + t < NN) { ptr[base + t] = excl; cursor[base + t] = excl; }
        __syncthreads();
        if (t == 0) running += wsum[31];
        __syncthreads();
    }
    if (t == 0) ptr[NN] = running;
}

__global__ void fill_kernel(const int* __restrict__ src, const int* __restrict__ dst,
                            int* __restrict__ cursor, int* __restrict__ csr) {
    int e = (blockIdx.x * blockDim.x + threadIdx.x) * 4;
#pragma unroll
    for (int q = 0; q < 4; q++) {
        int ee = e + q;
        if (ee < NE) {
            int p = atomicAdd(&cursor[__ldg(dst + ee)], 1);
            csr[p] = __ldg(src + ee);
        }
    }
}

// x [NN][165] fp32 -> fp16 [NN][192], zero-padded
__global__ void pad_kernel(const float* __restrict__ x, __half* __restrict__ xo) {
    int i = blockIdx.x * blockDim.x + threadIdx.x;
    if (i >= NN * (KP1 / 4)) return;
    int n = i / (KP1 / 4), c = (i % (KP1 / 4)) * 4;
    float v[4];
#pragma unroll
    for (int q = 0; q < 4; q++) {
        int cc = c + q;
        v[q] = (cc < INC) ? __ldg(&x[(size_t)n * INC + cc]) : 0.f;
    }
    *(uint32_t*)(xo + (size_t)n * KP1 + c)     = pack2h(v[0], v[1]);
    *(uint32_t*)(xo + (size_t)n * KP1 + c + 2) = pack2h(v[2], v[3]);
}

// ---------------------------------------------------------------------------
// Gather-aggregate (single fp16 plane): z[n] = f[n] + sum_nbr f[nbr].
// Warp per node; lane covers one uint4 (8 fp16 columns). fp32 accum.
// ---------------------------------------------------------------------------
template<int RU4>   // uint4s per row (24 for K=192, 32 for K=256)
__global__ void gather_kernel(const uint4* __restrict__ f,
                              const int* __restrict__ ptr, const int* __restrict__ csr,
                              uint4* __restrict__ z) {
    int n = blockIdx.x * (blockDim.x >> 5) + (threadIdx.x >> 5);
    if (n >= NN) return;
    const int lane = threadIdx.x & 31;
    if (lane >= RU4) return;
    float a[8] = {0, 0, 0, 0, 0, 0, 0, 0};
    acc8(a, __ldg(f + (size_t)n * RU4 + lane));
    const int e0 = __ldg(ptr + n), e1 = __ldg(ptr + n + 1);
    int j = e0;
    for (; j + 3 < e1; j += 4) {
        const size_t b0 = (size_t)__ldg(csr + j)     * RU4;
        const size_t b1 = (size_t)__ldg(csr + j + 1) * RU4;
        const size_t b2 = (size_t)__ldg(csr + j + 2) * RU4;
        const size_t b3 = (size_t)__ldg(csr + j + 3) * RU4;
        uint4 v0 = __ldg(f + b0 + lane), v1 = __ldg(f + b1 + lane);
        uint4 v2 = __ldg(f + b2 + lane), v3 = __ldg(f + b3 + lane);
        acc8(a, v0); acc8(a, v1); acc8(a, v2); acc8(a, v3);
    }
    for (; j < e1; j++) {
        const size_t b0 = (size_t)__ldg(csr + j) * RU4;
        acc8(a, __ldg(f + b0 + lane));
    }
    uint4 o;
    o.x = pack2h(a[0], a[1]);
    o.y = pack2h(a[2], a[3]);
    o.z = pack2h(a[4], a[5]);
    o.w = pack2h(a[6], a[7]);
    z[(size_t)n * RU4 + lane] = o;
}

// ---------------------------------------------------------------------------
// Weight prep: W[K,N] fp32 -> W^T fp16 (single plane), [N][Kp], zero-padded.
// ---------------------------------------------------------------------------
__global__ void prep_w_kernel(const float* __restrict__ W,
                              __half* __restrict__ hi,
                              int K, int N, int Kp) {
    int i = blockIdx.x * blockDim.x + threadIdx.x;
    if (i >= N * Kp) return;
    int n = i / Kp, k = i % Kp;
    float w = (k < K) ? __ldg(&W[(size_t)k * N + n]) : 0.f;
    hi[i] = __float2half_rn(w);
}

__global__ void init_out_kernel(float* __restrict__ out, const float* __restrict__ b2) {
    int i = blockIdx.x * blockDim.x + threadIdx.x;
    if (i < NN * 2) out[i] = __ldg(b2 + (i & 1));
}

// ---------------------------------------------------------------------------
// 2-stage cp.async pipelined warp-MMA GEMM: C = A @ B, fp16 x fp16, fp32 acc.
// Stage = 36.9 KB, 2 stages = 73.7 KB -> 2 CTAs/SM (pipeline + cross-CTA overlap).
// CTA tile 128x128, 8 warps 4Mx2N, warp tile 32x64.
// Non-OUTP epilogue: relu(acc+bias) -> single fp16 plane.
// OUTP: relu(acc+bias) projected on w2[256][2], atomicAdd into Cout[M][2].
// ---------------------------------------------------------------------------
#define SROW 72
#define SMAT (128 * SROW * 2)      // 18432 B per tile
#define OFF_A 0
#define OFF_B (SMAT)
#define STG (2 * SMAT)             // 36864 B per stage
#define SMTOT (2 * STG)            // 73728 B

template<bool OUTP>
__global__ __launch_bounds__(256, 2)
void mma_gemm_kernel(const __half* __restrict__ A, int lda,
                     const __half* __restrict__ B, int Kp,
                     const float* __restrict__ bias,
                     __half* __restrict__ C,
                     float* __restrict__ Cout, int M,
                     const float* __restrict__ w2) {
    extern __shared__ __align__(16) char smem[];
    const uint32_t sb = smem_u32(smem);
    const int tid = threadIdx.x, wid = tid >> 5, lane = tid & 31;

    const int bm0 = blockIdx.y * 128;
    const int n0 = blockIdx.x * 128;

    const int arow = tid >> 1;
    const int acol0 = (tid & 1) * 32;
    const int mw = (wid >> 1) * 32;
    const int nw = (wid & 1) * 64;

    const int gRow = bm0 + arow;
    const __half* pA = A + (size_t)(gRow < M ? gRow : 0) * lda + acol0;
    const __half* pB = B + (size_t)(n0 + arow) * Kp + acol0;
    const uint32_t sdst = sb + (uint32_t)(arow * SROW + acol0) * 2;

    const int nchunks = Kp >> 6;

#define PREFETCH(CH)  do { \
        const int _k0 = (CH) << 6; \
        const uint32_t _d = sdst + ((CH) & 1) * STG; \
        _Pragma("unroll") \
        for (int q = 0; q < 4; q++) { \
            cp16(_d + OFF_A + q * 16, pA + _k0 + q * 8); \
            cp16(_d + OFF_B + q * 16, pB + _k0 + q * 8); \
        } \
    } while (0)

    PREFETCH(0);
    asm volatile("cp.async.commit_group;" ::: "memory");
    PREFETCH(1);
    asm volatile("cp.async.commit_group;" ::: "memory");

    float acc[2][8][4];
#pragma unroll
    for (int ms = 0; ms < 2; ms++)
#pragma unroll
        for (int ns = 0; ns < 8; ns++)
#pragma unroll
            for (int q = 0; q < 4; q++) acc[ms][ns][q] = 0.f;

    const int l7 = lane & 7;
    const int aRowAdd = ((lane >> 3) & 1) * 8;
    const int aKAdd = (lane >> 4) * 8;
    const int bl = lane & 15;
    const int bRow = bl & 7;
    const int bKAdd = ((bl >> 3) & 1) * 8;

    for (int ch = 0; ch < nchunks; ch++) {
        asm volatile("cp.async.wait_group 1;" ::: "memory");
        __syncthreads();

        const uint32_t st = sb + (ch & 1) * STG;
#pragma unroll
        for (int kk = 0; kk < 64; kk += 16) {
            uint32_t av[2][4], bv[8][2];
#pragma unroll
            for (int ms = 0; ms < 2; ms++) {
                uint32_t ra = st + (uint32_t)((mw + ms * 16 + l7 + aRowAdd) * SROW + kk + aKAdd) * 2;
                ldm_x4(av[ms], ra + OFF_A);
            }
#pragma unroll
            for (int ns = 0; ns < 8; ns++) {
                uint32_t rb = st + (uint32_t)((nw + ns * 8 + bRow) * SROW + kk + bKAdd) * 2;
                ldm_x2(bv[ns], rb + OFF_B);
            }
#pragma unroll
            for (int ms = 0; ms < 2; ms++)
#pragma unroll
                for (int ns = 0; ns < 8; ns++)
                    mma_f16(acc[ms][ns], av[ms], bv[ns]);
        }
        __syncthreads();
        if (ch + 2 < nchunks) PREFETCH(ch + 2);
        asm volatile("cp.async.commit_group;" ::: "memory");
    }
#undef PREFETCH

    const int r = lane >> 2;
    const int cp = (lane & 3) * 2;

    if (OUTP) {
        float s[2][2][2];
#pragma unroll
        for (int ms = 0; ms < 2; ms++)
#pragma unroll
            for (int rh = 0; rh < 2; rh++) { s[ms][rh][0] = 0.f; s[ms][rh][1] = 0.f; }
#pragma unroll
        for (int ms = 0; ms < 2; ms++)
#pragma unroll
            for (int ns = 0; ns < 8; ns++) {
                const int col = n0 + nw + ns * 8 + cp;
                const float2 bb = *(const float2*)(bias + col);
                const float2 w0 = *(const float2*)(w2 + col * 2);
                const float2 w1 = *(const float2*)(w2 + (col + 1) * 2);
                float v0 = fmaxf(acc[ms][ns][0] + bb.x, 0.f);
                float v1 = fmaxf(acc[ms][ns][1] + bb.y, 0.f);
                float v2 = fmaxf(acc[ms][ns][2] + bb.x, 0.f);
                float v3 = fmaxf(acc[ms][ns][3] + bb.y, 0.f);
                s[ms][0][0] += v0 * w0.x + v1 * w1.x;
                s[ms][0][1] += v0 * w0.y + v1 * w1.y;
                s[ms][1][0] += v2 * w0.x + v3 * w1.x;
                s[ms][1][1] += v2 * w0.y + v3 * w1.y;
            }
#pragma unroll
        for (int ms = 0; ms < 2; ms++)
#pragma unroll
            for (int rh = 0; rh < 2; rh++)
#pragma unroll
                for (int oc = 0; oc < 2; oc++) {
                    float v = s[ms][rh][oc];
                    v += __shfl_xor_sync(0xffffffffu, v, 1);
                    v += __shfl_xor_sync(0xffffffffu, v, 2);
                    s[ms][rh][oc] = v;
                }
        if ((lane & 3) == 0) {
#pragma unroll
            for (int ms = 0; ms < 2; ms++)
#pragma unroll
                for (int rh = 0; rh < 2; rh++) {
                    const int row = bm0 + mw + ms * 16 + r + rh * 8;
                    if (row < M) {
                        atomicAdd(Cout + (size_t)row * 2 + 0, s[ms][rh][0]);
                        atomicAdd(Cout + (size_t)row * 2 + 1, s[ms][rh][1]);
                    }
                }
        }
    } else {
#pragma unroll
        for (int ms = 0; ms < 2; ms++)
#pragma unroll
            for (int ns = 0; ns < 8; ns++) {
                const int col = n0 + nw + ns * 8 + cp;
                const float2 bb = *(const float2*)(bias + col);
                const int row0 = bm0 + mw + ms * 16 + r;
                float v0 = fmaxf(acc[ms][ns][0] + bb.x, 0.f);
                float v1 = fmaxf(acc[ms][ns][1] + bb.y, 0.f);
                float v2 = fmaxf(acc[ms][ns][2] + bb.x, 0.f);
                float v3 = fmaxf(acc[ms][ns][3] + bb.y, 0.f);
#pragma unroll
                for (int rh = 0; rh < 2; rh++) {
                    const int row = row0 + rh * 8;
                    if (row >= M) continue;
                    *(uint32_t*)(C + (size_t)row * HID + col) =
                        pack2h(rh ? v2 : v0, rh ? v3 : v1);
                }
            }
    }
}

// ---------------------------------------------------------------------------
extern "C" void kernel_launch(void* const* d_in, const int* in_sizes, int n_in,
                              void* d_out, int out_size) {
    const float* x   = (const float*)d_in[0];
    const int*   ei  = (const int*)d_in[1];
    const float* W1a = (const float*)d_in[2];
    const float* b1a = (const float*)d_in[3];
    const float* W1b = (const float*)d_in[4];
    const float* b1b = (const float*)d_in[5];
    const float* W2a = (const float*)d_in[6];
    const float* b2a = (const float*)d_in[7];
    const float* W2b = (const float*)d_in[8];
    const float* b2b = (const float*)d_in[9];
    float* out = (float*)d_out;

    const int* src = ei;
    const int* dst = ei + NE;

    int *cnt, *ptr, *cursor, *csr;
    __half *xp, *z1, *h1, *h, *z2;
    __half *w1a, *w1b, *w2a;
    cudaGetSymbolAddress((void**)&cnt,    g_cnt);
    cudaGetSymbolAddress((void**)&ptr,    g_ptr);
    cudaGetSymbolAddress((void**)&cursor, g_cursor);
    cudaGetSymbolAddress((void**)&csr,    g_csr);
    cudaGetSymbolAddress((void**)&xp,     g_x);
    cudaGetSymbolAddress((void**)&z1,     g_z1);
    cudaGetSymbolAddress((void**)&h1,     g_h1);
    cudaGetSymbolAddress((void**)&h,      g_h);
    cudaGetSymbolAddress((void**)&z2,     g_z2);
    cudaGetSymbolAddress((void**)&w1a,    g_w1a);
    cudaGetSymbolAddress((void**)&w1b,    g_w1b);
    cudaGetSymbolAddress((void**)&w2a,    g_w2a);

    cudaFuncSetAttribute(mma_gemm_kernel<false>,
                         cudaFuncAttributeMaxDynamicSharedMemorySize, SMTOT);
    cudaFuncSetAttribute(mma_gemm_kernel<true>,
                         cudaFuncAttributeMaxDynamicSharedMemorySize, SMTOT);

    const dim3 gemmGrid(2, (NN + 127) / 128);
    const int edge4Grid = (NE / 4 + 255) / 256;
    const int nodeGrid = (NN + 7) / 8;

    // ---- CSR build + pad x ----
    cudaMemsetAsync(cnt, 0, sizeof(int) * NN);
    hist_kernel<<<edge4Grid, 256>>>(dst, cnt);
    pad_kernel<<<(NN * (KP1 / 4) + 255) / 256, 256>>>(x, xp);
    scan_kernel<<<1, 1024>>>(cnt, ptr, cursor);
    fill_kernel<<<edge4Grid, 256>>>(src, dst, cursor, csr);

    // ---- weight prep (single fp16 plane) ----
    prep_w_kernel<<<(HID * KP1 + 255) / 256, 256>>>(W1a, w1a, INC, HID, KP1);
    prep_w_kernel<<<(HID * HID + 255) / 256, 256>>>(W1b, w1b, HID, HID, HID);
    prep_w_kernel<<<(HID * HID + 255) / 256, 256>>>(W2a, w2a, HID, HID, HID);

    // ---- layer 1 ----
    gather_kernel<KP1 / 8><<<nodeGrid, 256>>>((const uint4*)xp, ptr, csr, (uint4*)z1);
    mma_gemm_kernel<false><<<gemmGrid, 256, SMTOT>>>(
        z1, KP1, w1a, KP1, b1a, h1, nullptr, NN, nullptr);
    mma_gemm_kernel<false><<<gemmGrid, 256, SMTOT>>>(
        h1, HID, w1b, HID, b1b, h, nullptr, NN, nullptr);

    // ---- layer 2 ----
    gather_kernel<HID / 8><<<nodeGrid, 256>>>((const uint4*)h, ptr, csr, (uint4*)z2);
    init_out_kernel<<<(NN * 2 + 255) / 256, 256>>>(out, b2b);
    mma_gemm_kernel<true><<<gemmGrid, 256, SMTOT>>>(
        z2, HID, w2a, HID, b2a, nullptr, out, NN, W2b);
}